// round 12
// baseline (speedup 1.0000x reference)
#include <cuda_runtime.h>
#include <cuda_fp16.h>
#include <cstdint>

// Problem constants
#define BSZ 4
#define CSZ 64
#define TSZ 1024
#define FSZ 128
#define HN  4
#define HIDN 4
#define CHN 16
#define NB  (HN*BSZ)      // 16 attention batches
#define DQK (HIDN*FSZ)    // 512
#define DV  (CHN*FSZ)     // 2048

// Scratch (device globals: allocation-free rule)
__device__ __half g_qh[(size_t)NB*TSZ*DQK];          // q hi (fp16)
__device__ __half g_ql[(size_t)NB*TSZ*DQK];          // q lo
__device__ __half g_kh[(size_t)NB*TSZ*DQK];          // k hi
__device__ __half g_kl[(size_t)NB*TSZ*DQK];          // k lo
__device__ __half g_vh[(size_t)NB*TSZ*DV];           // v fp16 [n][t][d]
__device__ float  g_s [(size_t)NB*TSZ*TSZ];          // logits fp32
__device__ __half g_sh[(size_t)NB*TSZ*TSZ];          // P fp16 [n][t][t']
__device__ __half g_aoh[(size_t)BSZ*CSZ*TSZ*FSZ];    // attention out, fp16

// ===========================================================================
// helpers
// ===========================================================================
__device__ __forceinline__ uint32_t smem_u32(const void* p) {
    uint32_t a;
    asm("{ .reg .u64 t; cvta.to.shared.u64 t, %1; cvt.u32.u64 %0, t; }" : "=r"(a) : "l"(p));
    return a;
}
__device__ __forceinline__ void ldsm4(uint32_t& r0, uint32_t& r1, uint32_t& r2, uint32_t& r3,
                                      uint32_t addr) {
    asm volatile("ldmatrix.sync.aligned.m8n8.x4.shared.b16 {%0,%1,%2,%3}, [%4];"
                 : "=r"(r0), "=r"(r1), "=r"(r2), "=r"(r3) : "r"(addr));
}
__device__ __forceinline__ void ldsm4t(uint32_t& r0, uint32_t& r1, uint32_t& r2, uint32_t& r3,
                                       uint32_t addr) {
    asm volatile("ldmatrix.sync.aligned.m8n8.x4.trans.shared.b16 {%0,%1,%2,%3}, [%4];"
                 : "=r"(r0), "=r"(r1), "=r"(r2), "=r"(r3) : "r"(addr));
}
// fp16 m16n8k16, fp32 accumulate
__device__ __forceinline__ void mma16(float* d, const uint32_t* a, uint32_t b0, uint32_t b1) {
    asm volatile("mma.sync.aligned.m16n8k16.row.col.f32.f16.f16.f32 "
                 "{%0,%1,%2,%3}, {%4,%5,%6,%7}, {%8,%9}, {%0,%1,%2,%3};"
                 : "+f"(d[0]), "+f"(d[1]), "+f"(d[2]), "+f"(d[3])
                 : "r"(a[0]), "r"(a[1]), "r"(a[2]), "r"(a[3]), "r"(b0), "r"(b1));
}
__device__ __forceinline__ void cp16(uint32_t dst, const void* src) {
    asm volatile("cp.async.cg.shared.global [%0], [%1], 16;" :: "r"(dst), "l"(src));
}
#define CP_COMMIT() asm volatile("cp.async.commit_group;" ::: "memory")
#define CP_WAIT0()  asm volatile("cp.async.wait_group 0;"  ::: "memory")
#define CP_WAIT1()  asm volatile("cp.async.wait_group 1;"  ::: "memory")

// fp16 hi/lo split of a float4 -> two packed uint2 (4 halves each)
__device__ __forceinline__ void split4(float4 v, uint2& hh, uint2& ll) {
    __half h0 = __float2half_rn(v.x), h1 = __float2half_rn(v.y);
    __half h2 = __float2half_rn(v.z), h3 = __float2half_rn(v.w);
    __half l0 = __float2half_rn(v.x - __half2float(h0));
    __half l1 = __float2half_rn(v.y - __half2float(h1));
    __half l2 = __float2half_rn(v.z - __half2float(h2));
    __half l3 = __float2half_rn(v.w - __half2float(h3));
    __half2 a = __halves2half2(h0, h1), b = __halves2half2(h2, h3);
    __half2 c = __halves2half2(l0, l1), d = __halves2half2(l2, l3);
    hh.x = *(uint32_t*)&a; hh.y = *(uint32_t*)&b;
    ll.x = *(uint32_t*)&c; ll.y = *(uint32_t*)&d;
}

// ===========================================================================
// GEMM 1: S = scale * Q K^T  (3xFP16 split, NT, 128x128, k-chunks of 32)
// ===========================================================================
#define QKC 32
#define QK_NCH (DQK/QKC)           // 16
#define A_PITCH 80                 // 64B data + 16B pad
#define QK_TILE (128*A_PITCH)      // 10240 B
#define QK_STAGE (4*QK_TILE)       // 40960 B

__global__ void __launch_bounds__(256, 2) gemm_qk_f16()
{
    extern __shared__ char smq[];
    const int tid = threadIdx.x, lane = tid & 31, warp = tid >> 5;
    const int wm = warp >> 2, wn = warp & 3;
    const int bz = blockIdx.z, m0 = blockIdx.y*128, n0 = blockIdx.x*128;
    const __half* Ah = g_qh + ((size_t)bz*TSZ + m0)*DQK;
    const __half* Al = g_ql + ((size_t)bz*TSZ + m0)*DQK;
    const __half* Bh = g_kh + ((size_t)bz*TSZ + n0)*DQK;
    const __half* Bl = g_kl + ((size_t)bz*TSZ + n0)*DQK;

    float acc[4][4][4];
    #pragma unroll
    for (int i = 0; i < 4; i++)
        #pragma unroll
        for (int j = 0; j < 4; j++)
            #pragma unroll
            for (int k = 0; k < 4; k++) acc[i][j][k] = 0.f;

    const uint32_t sbase = smem_u32(smq);
    const uint32_t aoff = (wm*64 + (lane & 15))*A_PITCH + (lane >> 4)*16;
    const uint32_t boff = (wn*32 + (lane & 7))*A_PITCH + (lane >> 3)*16;

    auto issue = [&](int c, int s) {
        uint32_t dst = sbase + s*QK_STAGE;
        #pragma unroll
        for (int i = 0; i < 2; i++) {
            int idx = tid + 256*i;
            int row = idx >> 2, seg = idx & 3;
            uint32_t d = row*A_PITCH + seg*16;
            size_t sa = (size_t)row*(DQK*2) + (size_t)c*(QKC*2) + seg*16;
            cp16(dst + d,             (const char*)Ah + sa);
            cp16(dst + QK_TILE + d,   (const char*)Al + sa);
            cp16(dst + 2*QK_TILE + d, (const char*)Bh + sa);
            cp16(dst + 3*QK_TILE + d, (const char*)Bl + sa);
        }
        CP_COMMIT();
    };

    issue(0, 0);
    for (int c = 0; c < QK_NCH; c++) {
        CP_WAIT0();
        __syncthreads();
        if (c + 1 < QK_NCH) issue(c+1, (c+1) & 1);
        const uint32_t so = sbase + (c & 1)*QK_STAGE;

        uint32_t bh[4][4], bl[4][4];
        #pragma unroll
        for (int in = 0; in < 4; in++) {
            ldsm4(bh[in][0], bh[in][1], bh[in][2], bh[in][3],
                  so + 2*QK_TILE + boff + in*(8*A_PITCH));
            ldsm4(bl[in][0], bl[in][1], bl[in][2], bl[in][3],
                  so + 3*QK_TILE + boff + in*(8*A_PITCH));
        }
        #pragma unroll
        for (int ks = 0; ks < 2; ks++) {
            uint32_t ah[4][4], al[4][4];
            #pragma unroll
            for (int im = 0; im < 4; im++) {
                ldsm4(ah[im][0], ah[im][1], ah[im][2], ah[im][3],
                      so + aoff + im*(16*A_PITCH) + ks*32);
                ldsm4(al[im][0], al[im][1], al[im][2], al[im][3],
                      so + QK_TILE + aoff + im*(16*A_PITCH) + ks*32);
            }
            #pragma unroll
            for (int im = 0; im < 4; im++)
                #pragma unroll
                for (int in = 0; in < 4; in++) {
                    mma16(acc[im][in], ah[im], bh[in][2*ks], bh[in][2*ks+1]);
                    mma16(acc[im][in], ah[im], bl[in][2*ks], bl[in][2*ks+1]);
                    mma16(acc[im][in], al[im], bh[in][2*ks], bh[in][2*ks+1]);
                }
        }
    }

    const float scale = 0.0441941738241592f;   // 1/sqrt(512)
    float* Cb = g_s + (size_t)bz*TSZ*TSZ;
    const int mbase = m0 + wm*64, nbase = n0 + wn*32;
    #pragma unroll
    for (int im = 0; im < 4; im++)
        #pragma unroll
        for (int in = 0; in < 4; in++) {
            int rr = mbase + im*16 + (lane >> 2);
            int cc = nbase + in*8 + (lane & 3)*2;
            float2 o0 = make_float2(acc[im][in][0]*scale, acc[im][in][1]*scale);
            float2 o1 = make_float2(acc[im][in][2]*scale, acc[im][in][3]*scale);
            *(float2*)(Cb + (size_t)rr*TSZ + cc)     = o0;
            *(float2*)(Cb + (size_t)(rr+8)*TSZ + cc) = o1;
        }
}

// ===========================================================================
// GEMM 2: O = P V  (single FP16; V via ldmatrix.trans; K-chunk 64; 3-stage)
// ===========================================================================
#define PVC 64
#define PV_NCH (TSZ/PVC)           // 16
#define PVA_PITCH 144
#define PVB_PITCH 272
#define PVA_TILE (128*PVA_PITCH)   // 18432
#define PVB_TILE (64*PVB_PITCH)    // 17408
#define PV_STAGE (PVA_TILE + PVB_TILE)  // 35840

__global__ void __launch_bounds__(256, 2) gemm_pv_f16()
{
    extern __shared__ char smp[];
    const int tid = threadIdx.x, lane = tid & 31, warp = tid >> 5;
    const int wm = warp >> 2, wn = warp & 3;
    const int bz = blockIdx.z, m0 = blockIdx.y*128, n0 = blockIdx.x*128;
    const __half* A = g_sh + (size_t)bz*TSZ*TSZ + (size_t)m0*TSZ;
    const __half* B = g_vh + (size_t)bz*TSZ*DV;

    float acc[4][4][4];
    #pragma unroll
    for (int i = 0; i < 4; i++)
        #pragma unroll
        for (int j = 0; j < 4; j++)
            #pragma unroll
            for (int k = 0; k < 4; k++) acc[i][j][k] = 0.f;

    const uint32_t sbase = smem_u32(smp);
    const uint32_t aoff = (wm*64 + (lane & 15))*PVA_PITCH + (lane >> 4)*16;
    const uint32_t btoff = PVA_TILE + lane*PVB_PITCH + wn*64;

    auto issue = [&](int c, int s) {
        uint32_t dst = sbase + s*PV_STAGE;
        #pragma unroll
        for (int i = 0; i < 4; i++) {
            int idx = tid + 256*i;
            int ar = idx >> 3, as = idx & 7;
            cp16(dst + ar*PVA_PITCH + as*16,
                 (const char*)A + (size_t)ar*(TSZ*2) + (size_t)c*(PVC*2) + as*16);
            int br = idx >> 4, bs = idx & 15;
            cp16(dst + PVA_TILE + br*PVB_PITCH + bs*16,
                 (const char*)B + ((size_t)(c*PVC + br))*(DV*2) + (size_t)n0*2 + bs*16);
        }
        CP_COMMIT();
    };

    issue(0, 0);
    issue(1, 1);
    for (int c = 0; c < PV_NCH; c++) {
        if (c + 1 < PV_NCH) CP_WAIT1();
        else                CP_WAIT0();
        __syncthreads();
        if (c + 2 < PV_NCH) issue(c+2, (c+2) % 3);
        const uint32_t so = sbase + (c % 3)*PV_STAGE;

        #pragma unroll
        for (int half = 0; half < 2; half++) {
            uint32_t bt[4][4];
            #pragma unroll
            for (int in = 0; in < 4; in++)
                ldsm4t(bt[in][0], bt[in][1], bt[in][2], bt[in][3],
                       so + btoff + half*(32*PVB_PITCH) + in*16);
            #pragma unroll
            for (int ks = 0; ks < 2; ks++) {
                uint32_t a[4][4];
                #pragma unroll
                for (int im = 0; im < 4; im++)
                    ldsm4(a[im][0], a[im][1], a[im][2], a[im][3],
                          so + aoff + im*(16*PVA_PITCH) + (half*2 + ks)*32);
                #pragma unroll
                for (int im = 0; im < 4; im++)
                    #pragma unroll
                    for (int in = 0; in < 4; in++)
                        mma16(acc[im][in], a[im], bt[in][2*ks], bt[in][2*ks+1]);
            }
        }
    }

    const int h = bz >> 2, bb = bz & 3;
    const int cc_ch = h*CHN + blockIdx.x;
    const int mbase = m0 + wm*64, nbase = wn*32;
    __half* Ob = g_aoh + ((size_t)(bb*CSZ + cc_ch)*TSZ)*FSZ;
    #pragma unroll
    for (int im = 0; im < 4; im++)
        #pragma unroll
        for (int in = 0; in < 4; in++) {
            int rr = mbase + im*16 + (lane >> 2);
            int ff = nbase + in*8 + (lane & 3)*2;
            *(__half2*)(Ob + (size_t)rr*FSZ + ff) =
                __floats2half2_rn(acc[im][in][0], acc[im][in][1]);
            *(__half2*)(Ob + (size_t)(rr+8)*FSZ + ff) =
                __floats2half2_rn(acc[im][in][2], acc[im][in][3]);
        }
}

// ===========================================================================
// QKV part 1: q,k rows (32). TWO t's per block. 3xFP16 m16n8k16.
// ===========================================================================
#define QW_PITCH 144
#define QX_PITCH 272
#define QX_T (64*QX_PITCH)                   // 17408
#define QKQ_WH 0
#define QKQ_WL (32*QW_PITCH)                 // 4608
#define QKQ_XH (2*32*QW_PITCH)               // 9216
#define QKQ_XSZ (2*QX_T)                     // 34816
#define QKQ_XL (QKQ_XH + QKQ_XSZ)            // 44032
#define QKQ_SMEM (QKQ_XH + 2*QKQ_XSZ)        // 78848

__global__ void __launch_bounds__(256) qkv_qk_part(
    const float* __restrict__ x,
    const float* __restrict__ Wq, const float* __restrict__ bq,
    const float* __restrict__ aq, const float* __restrict__ gq, const float* __restrict__ beq,
    const float* __restrict__ Wk, const float* __restrict__ bk,
    const float* __restrict__ ak, const float* __restrict__ gk, const float* __restrict__ bek)
{
    extern __shared__ char sm[];
    __shared__ float rowred[64];
    __shared__ float stats[16];
    __shared__ float biasS[32], alphS[32];

    const int tid = threadIdx.x, lane = tid & 31, warp = tid >> 5;
    const int wm = warp >> 2, wn = warp & 3;
    const int ly = lane >> 2, lx = lane & 3;
    const int b = blockIdx.x >> 9, t0 = (blockIdx.x & 511)*2;

    if (tid < 32) {
        if (tid < 16) { biasS[tid] = bq[tid];    alphS[tid] = aq[tid>>2]; }
        else          { biasS[tid] = bk[tid-16]; alphS[tid] = ak[(tid-16)>>2]; }
    }

    // W: 32 rows x 64 floats -> fp16 hi/lo (512 float4, 2/thread)
    #pragma unroll
    for (int j = 0; j < 2; j++) {
        int idx = tid + 256*j;
        int row = idx >> 4, c4 = idx & 15;
        const float* src = (row < 16) ? (Wq + row*CSZ) : (Wk + (row-16)*CSZ);
        float4 w = *(const float4*)(src + c4*4);
        uint2 hh, ll; split4(w, hh, ll);
        *(uint2*)(sm + QKQ_WH + row*QW_PITCH + c4*8) = hh;
        *(uint2*)(sm + QKQ_WL + row*QW_PITCH + c4*8) = ll;
    }
    // X: both t's (4096 float4, 16/thread)
    #pragma unroll
    for (int j = 0; j < 16; j++) {
        int idx = tid + 256*j;
        int tt = idx >> 11, rem = idx & 2047;
        int c = rem >> 5, f4 = rem & 31;
        float4 v = *(const float4*)(x + (((size_t)(b*CSZ + c))*TSZ + t0 + tt)*FSZ + f4*4);
        uint2 hh, ll; split4(v, hh, ll);
        *(uint2*)(sm + QKQ_XH + tt*QX_T + c*QX_PITCH + f4*8) = hh;
        *(uint2*)(sm + QKQ_XL + tt*QX_T + c*QX_PITCH + f4*8) = ll;
    }
    __syncthreads();

    const uint32_t sbase = smem_u32(sm);
    const uint32_t awoff = sbase + QKQ_WH + (wm*16 + (lane & 15))*QW_PITCH + (lane >> 4)*16;

    for (int tt = 0; tt < 2; tt++) {
        const int t = t0 + tt;
        if (tid < 64) rowred[tid] = 0.f;
        __syncthreads();

        const uint32_t bxoff = sbase + QKQ_XH + tt*QX_T + lane*QX_PITCH + wn*64;

        float acc[4][4];
        #pragma unroll
        for (int j = 0; j < 4; j++)
            #pragma unroll
            for (int k = 0; k < 4; k++) acc[j][k] = 0.f;

        #pragma unroll
        for (int half = 0; half < 2; half++) {
            uint32_t bth[4][4], btl[4][4];
            #pragma unroll
            for (int in = 0; in < 4; in++) {
                ldsm4t(bth[in][0], bth[in][1], bth[in][2], bth[in][3],
                       bxoff + half*(32*QX_PITCH) + in*16);
                ldsm4t(btl[in][0], btl[in][1], btl[in][2], btl[in][3],
                       bxoff + QKQ_XSZ + half*(32*QX_PITCH) + in*16);
            }
            #pragma unroll
            for (int ks = 0; ks < 2; ks++) {
                const int kstep = half*2 + ks;
                uint32_t ah[4], al[4];
                ldsm4(ah[0], ah[1], ah[2], ah[3], awoff + kstep*32);
                ldsm4(al[0], al[1], al[2], al[3],
                      awoff + (QKQ_WL - QKQ_WH) + kstep*32);
                #pragma unroll
                for (int in = 0; in < 4; in++) {
                    mma16(acc[in], ah, bth[in][2*ks], bth[in][2*ks+1]);
                    mma16(acc[in], ah, btl[in][2*ks], btl[in][2*ks+1]);
                    mma16(acc[in], al, bth[in][2*ks], bth[in][2*ks+1]);
                }
            }
        }

        // bias + PReLU + per-row partial sums
        float rs[2] = {0.f, 0.f}, rq[2] = {0.f, 0.f};
        #pragma unroll
        for (int hh = 0; hh < 2; hh++) {
            int r = wm*16 + ly + hh*8;
            float bi = biasS[r], alp = alphS[r];
            #pragma unroll
            for (int in = 0; in < 4; in++)
                #pragma unroll
                for (int e = 0; e < 2; e++) {
                    float y = acc[in][hh*2+e] + bi;
                    y = y > 0.f ? y : alp*y;
                    acc[in][hh*2+e] = y;
                    rs[hh] += y; rq[hh] += y*y;
                }
        }
        #pragma unroll
        for (int hh = 0; hh < 2; hh++) {
            float s = rs[hh], q = rq[hh];
            s += __shfl_xor_sync(0xffffffffu, s, 1); q += __shfl_xor_sync(0xffffffffu, q, 1);
            s += __shfl_xor_sync(0xffffffffu, s, 2); q += __shfl_xor_sync(0xffffffffu, q, 2);
            if (lx == 0) {
                int r = wm*16 + ly + hh*8;
                atomicAdd(&rowred[2*r], s); atomicAdd(&rowred[2*r+1], q);
            }
        }
        __syncthreads();
        if (tid < 8) {
            int st = tid*4;
            float s = 0.f, q = 0.f;
            for (int r = st; r < st+4; r++) { s += rowred[2*r]; q += rowred[2*r+1]; }
            const float inv = 1.f/(4*FSZ);
            float mean = s*inv, var = q*inv - mean*mean;
            stats[2*tid] = mean; stats[2*tid+1] = rsqrtf(var + 1e-5f);
        }
        __syncthreads();

        // normalize + store q/k fp16 hi/lo
        #pragma unroll
        for (int hh = 0; hh < 2; hh++) {
            int r = wm*16 + ly + hh*8;
            int grp = r >> 2;
            float mean = stats[2*grp], rstd = stats[2*grp+1];
            int jrow = (r < 16) ? r : r - 16;
            const float* gvec  = (r < 16) ? gq  : gk;
            const float* bevec = (r < 16) ? beq : bek;
            size_t off = (((size_t)((jrow>>2)*BSZ + b)*TSZ + t)*DQK) + (jrow&3)*FSZ;
            __half* dh = (r < 16) ? (g_qh + off) : (g_kh + off);
            __half* dl = (r < 16) ? (g_ql + off) : (g_kl + off);
            #pragma unroll
            for (int in = 0; in < 4; in++) {
                int c = wn*32 + in*8 + lx*2;
                float y0 = (acc[in][hh*2+0]-mean)*rstd*gvec[jrow*FSZ+c]   + bevec[jrow*FSZ+c];
                float y1 = (acc[in][hh*2+1]-mean)*rstd*gvec[jrow*FSZ+c+1] + bevec[jrow*FSZ+c+1];
                __half h0 = __float2half_rn(y0), h1 = __float2half_rn(y1);
                __half l0 = __float2half_rn(y0 - __half2float(h0));
                __half l1 = __float2half_rn(y1 - __half2float(h1));
                *(__half2*)(dh + c) = __halves2half2(h0, h1);
                *(__half2*)(dl + c) = __halves2half2(l0, l1);
            }
        }
        __syncthreads();
    }
}

// ===========================================================================
// QKV part 2: v rows (64). TWO t's per block. 3xFP16 m16n8k16.
// ===========================================================================
#define QV_WH 0
#define QV_WL (64*QW_PITCH)                  // 9216
#define QV_XH (2*64*QW_PITCH)                // 18432
#define QV_XSZ (2*QX_T)                      // 34816
#define QV_XL (QV_XH + QV_XSZ)               // 53248
#define QV_SMEM (QV_XH + 2*QV_XSZ)           // 88064

__global__ void __launch_bounds__(256) qkv_v_part(
    const float* __restrict__ x,
    const float* __restrict__ Wv, const float* __restrict__ bv,
    const float* __restrict__ av, const float* __restrict__ gv, const float* __restrict__ bev)
{
    extern __shared__ char sm[];
    __shared__ float rowred[128];
    __shared__ float stats[8];
    __shared__ float biasS[64], alphS[64];

    const int tid = threadIdx.x, lane = tid & 31, warp = tid >> 5;
    const int wm = warp >> 2, wn = warp & 3;
    const int ly = lane >> 2, lx = lane & 3;
    const int b = blockIdx.x >> 9, t0 = (blockIdx.x & 511)*2;

    if (tid < 64) { biasS[tid] = bv[tid]; alphS[tid] = av[tid>>4]; }

    // W: 64 rows x 64 floats (1024 float4, 4/thread)
    #pragma unroll
    for (int j = 0; j < 4; j++) {
        int idx = tid + 256*j;
        int row = idx >> 4, c4 = idx & 15;
        float4 w = *(const float4*)(Wv + row*CSZ + c4*4);
        uint2 hh, ll; split4(w, hh, ll);
        *(uint2*)(sm + QV_WH + row*QW_PITCH + c4*8) = hh;
        *(uint2*)(sm + QV_WL + row*QW_PITCH + c4*8) = ll;
    }
    // X: both t's (4096 float4, 16/thread)
    #pragma unroll
    for (int j = 0; j < 16; j++) {
        int idx = tid + 256*j;
        int tt = idx >> 11, rem = idx & 2047;
        int c = rem >> 5, f4 = rem & 31;
        float4 v = *(const float4*)(x + (((size_t)(b*CSZ + c))*TSZ + t0 + tt)*FSZ + f4*4);
        uint2 hh, ll; split4(v, hh, ll);
        *(uint2*)(sm + QV_XH + tt*QX_T + c*QX_PITCH + f4*8) = hh;
        *(uint2*)(sm + QV_XL + tt*QX_T + c*QX_PITCH + f4*8) = ll;
    }
    __syncthreads();

    const uint32_t sbase = smem_u32(sm);
    const uint32_t awoff = sbase + QV_WH + (wm*32 + (lane & 15))*QW_PITCH + (lane >> 4)*16;

    for (int tt = 0; tt < 2; tt++) {
        const int t = t0 + tt;
        if (tid < 128) rowred[tid] = 0.f;
        __syncthreads();

        const uint32_t bxoff = sbase + QV_XH + tt*QX_T + lane*QX_PITCH + wn*64;

        float acc[2][4][4];
        #pragma unroll
        for (int i = 0; i < 2; i++)
            #pragma unroll
            for (int j = 0; j < 4; j++)
                #pragma unroll
                for (int k = 0; k < 4; k++) acc[i][j][k] = 0.f;

        #pragma unroll
        for (int half = 0; half < 2; half++) {
            uint32_t bth[4][4], btl[4][4];
            #pragma unroll
            for (int in = 0; in < 4; in++) {
                ldsm4t(bth[in][0], bth[in][1], bth[in][2], bth[in][3],
                       bxoff + half*(32*QX_PITCH) + in*16);
                ldsm4t(btl[in][0], btl[in][1], btl[in][2], btl[in][3],
                       bxoff + QV_XSZ + half*(32*QX_PITCH) + in*16);
            }
            #pragma unroll
            for (int ks = 0; ks < 2; ks++) {
                const int kstep = half*2 + ks;
                uint32_t ah[2][4], al[2][4];
                #pragma unroll
                for (int im = 0; im < 2; im++) {
                    ldsm4(ah[im][0], ah[im][1], ah[im][2], ah[im][3],
                          awoff + im*(16*QW_PITCH) + kstep*32);
                    ldsm4(al[im][0], al[im][1], al[im][2], al[im][3],
                          awoff + (QV_WL - QV_WH) + im*(16*QW_PITCH) + kstep*32);
                }
                #pragma unroll
                for (int im = 0; im < 2; im++)
                    #pragma unroll
                    for (int in = 0; in < 4; in++) {
                        mma16(acc[im][in], ah[im], bth[in][2*ks], bth[in][2*ks+1]);
                        mma16(acc[im][in], ah[im], btl[in][2*ks], btl[in][2*ks+1]);
                        mma16(acc[im][in], al[im], bth[in][2*ks], bth[in][2*ks+1]);
                    }
            }
        }

        // bias + PReLU + per-row partial sums
        float rs[2][2], rq[2][2];
        #pragma unroll
        for (int im = 0; im < 2; im++) { rs[im][0]=rs[im][1]=0.f; rq[im][0]=rq[im][1]=0.f; }
        #pragma unroll
        for (int im = 0; im < 2; im++)
            #pragma unroll
            for (int hh = 0; hh < 2; hh++) {
                int r = wm*32 + im*16 + ly + hh*8;
                float bi = biasS[r], alp = alphS[r];
                #pragma unroll
                for (int in = 0; in < 4; in++)
                    #pragma unroll
                    for (int e = 0; e < 2; e++) {
                        float y = acc[im][in][hh*2+e] + bi;
                        y = y > 0.f ? y : alp*y;
                        acc[im][in][hh*2+e] = y;
                        rs[im][hh] += y; rq[im][hh] += y*y;
                    }
            }
        #pragma unroll
        for (int im = 0; im < 2; im++)
            #pragma unroll
            for (int hh = 0; hh < 2; hh++) {
                float s = rs[im][hh], q = rq[im][hh];
                s += __shfl_xor_sync(0xffffffffu, s, 1); q += __shfl_xor_sync(0xffffffffu, q, 1);
                s += __shfl_xor_sync(0xffffffffu, s, 2); q += __shfl_xor_sync(0xffffffffu, q, 2);
                if (lx == 0) {
                    int r = wm*32 + im*16 + ly + hh*8;
                    atomicAdd(&rowred[2*r], s); atomicAdd(&rowred[2*r+1], q);
                }
            }
        __syncthreads();
        if (tid < 4) {
            int st = tid*16;
            float s = 0.f, q = 0.f;
            for (int r = st; r < st+16; r++) { s += rowred[2*r]; q += rowred[2*r+1]; }
            const float inv = 1.f/(16*FSZ);
            float mean = s*inv, var = q*inv - mean*mean;
            stats[2*tid] = mean; stats[2*tid+1] = rsqrtf(var + 1e-5f);
        }
        __syncthreads();

        // normalize + store v fp16
        #pragma unroll
        for (int im = 0; im < 2; im++)
            #pragma unroll
            for (int hh = 0; hh < 2; hh++) {
                int r = wm*32 + im*16 + ly + hh*8;
                int grp = r >> 4;
                float mean = stats[2*grp], rstd = stats[2*grp+1];
                __half* dst = g_vh + (((size_t)(grp*BSZ + b)*TSZ + t)*DV) + (r&15)*FSZ;
                #pragma unroll
                for (int in = 0; in < 4; in++) {
                    int c = wn*32 + in*8 + lx*2;
                    float y0 = (acc[im][in][hh*2+0]-mean)*rstd*gv[r*FSZ+c]   + bev[r*FSZ+c];
                    float y1 = (acc[im][in][hh*2+1]-mean)*rstd*gv[r*FSZ+c+1] + bev[r*FSZ+c+1];
                    *(__half2*)(dst + c) = __floats2half2_rn(y0, y1);
                }
            }
        __syncthreads();
    }
}

// ===========================================================================
// PROJ: per block TWO t's. Y[64,128] = Wp[64,64] @ AO[64,128] per t.
//   AO is fp16 (g_aoh) -> X loaded raw via cp.async; 2-term split (W only).
// ===========================================================================
#define PJX_PITCH 272
#define PJX_T (64*PJX_PITCH)                 // 17408
#define PJ_WH 0
#define PJ_WL (64*QW_PITCH)                  // 9216
#define PJ_X  (2*64*QW_PITCH)                // 18432
#define PJ_SMEM (PJ_X + 2*PJX_T)             // 53248

__global__ void __launch_bounds__(256) proj_f16(
    const float* __restrict__ x, const float* __restrict__ Wp,
    const float* __restrict__ bp, const float* __restrict__ ap,
    const float* __restrict__ gp, const float* __restrict__ bep,
    float* __restrict__ out)
{
    extern __shared__ char sm[];
    __shared__ float red[2];
    __shared__ float statv[2];

    const int tid = threadIdx.x, lane = tid & 31, warp = tid >> 5;
    const int wm = warp >> 2, wn = warp & 3;
    const int ly = lane >> 2, lx = lane & 3;
    const int b = blockIdx.x >> 9, t0 = (blockIdx.x & 511)*2;

    const uint32_t sbase = smem_u32(sm);

    // X = AO (fp16): raw cp.async, both t's.
    #pragma unroll
    for (int j = 0; j < 8; j++) {
        int idx = tid + 256*j;
        int tt = idx >> 10, rem = idx & 1023;
        int c = rem >> 4, seg = rem & 15;
        cp16(sbase + PJ_X + tt*PJX_T + c*PJX_PITCH + seg*16,
             (const char*)(g_aoh + (((size_t)(b*CSZ + c))*TSZ + t0 + tt)*FSZ) + seg*16);
    }
    CP_COMMIT();

    // W: 64 rows x 64 floats (hi/lo)
    #pragma unroll
    for (int j = 0; j < 4; j++) {
        int idx = tid + 256*j;
        int row = idx >> 4, c4 = idx & 15;
        float4 w = *(const float4*)(Wp + row*CSZ + c4*4);
        uint2 hh, ll; split4(w, hh, ll);
        *(uint2*)(sm + PJ_WH + row*QW_PITCH + c4*8) = hh;
        *(uint2*)(sm + PJ_WL + row*QW_PITCH + c4*8) = ll;
    }
    CP_WAIT0();
    __syncthreads();

    const uint32_t awoff = sbase + PJ_WH + (wm*32 + (lane & 15))*QW_PITCH + (lane >> 4)*16;

    for (int tt = 0; tt < 2; tt++) {
        const int t = t0 + tt;
        if (tid < 2) red[tid] = 0.f;
        __syncthreads();

        const uint32_t bxoff = sbase + PJ_X + tt*PJX_T + lane*PJX_PITCH + wn*64;

        float acc[2][4][4];
        #pragma unroll
        for (int i = 0; i < 2; i++)
            #pragma unroll
            for (int j = 0; j < 4; j++)
                #pragma unroll
                for (int k = 0; k < 4; k++) acc[i][j][k] = 0.f;

        #pragma unroll
        for (int half = 0; half < 2; half++) {
            uint32_t bt[4][4];
            #pragma unroll
            for (int in = 0; in < 4; in++)
                ldsm4t(bt[in][0], bt[in][1], bt[in][2], bt[in][3],
                       bxoff + half*(32*PJX_PITCH) + in*16);
            #pragma unroll
            for (int ks = 0; ks < 2; ks++) {
                const int kstep = half*2 + ks;
                uint32_t ah[2][4], al[2][4];
                #pragma unroll
                for (int im = 0; im < 2; im++) {
                    ldsm4(ah[im][0], ah[im][1], ah[im][2], ah[im][3],
                          awoff + im*(16*QW_PITCH) + kstep*32);
                    ldsm4(al[im][0], al[im][1], al[im][2], al[im][3],
                          awoff + (PJ_WL - PJ_WH) + im*(16*QW_PITCH) + kstep*32);
                }
                #pragma unroll
                for (int im = 0; im < 2; im++)
                    #pragma unroll
                    for (int in = 0; in < 4; in++) {
                        mma16(acc[im][in], ah[im], bt[in][2*ks], bt[in][2*ks+1]);
                        mma16(acc[im][in], al[im], bt[in][2*ks], bt[in][2*ks+1]);
                    }
            }
        }

        const float alp = ap[0];
        float s1 = 0.f, s2 = 0.f;
        #pragma unroll
        for (int im = 0; im < 2; im++)
            #pragma unroll
            for (int hh = 0; hh < 2; hh++) {
                int r = wm*32 + im*16 + ly + hh*8;
                float bi = bp[r];
                #pragma unroll
                for (int in = 0; in < 4; in++)
                    #pragma unroll
                    for (int e = 0; e < 2; e++) {
                        float y = acc[im][in][hh*2+e] + bi;
                        y = y > 0.f ? y : alp*y;
                        acc[im][in][hh*2+e] = y;
                        s1 += y; s2 += y*y;
                    }
            }
        #pragma unroll
        for (int off = 16; off; off >>= 1) {
            s1 += __shfl_xor_sync(0xffffffffu, s1, off);
            s2 += __shfl_xor_sync(0xffffffffu, s2, off);
        }
        if (lane == 0) { atomicAdd(&red[0], s1); atomicAdd(&red[1], s2); }
        __syncthreads();
        if (tid == 0) {
            const float invn = 1.f/(CSZ*FSZ);
            float mean = red[0]*invn, var = red[1]*invn - mean*mean;
            statv[0] = mean; statv[1] = rsqrtf(var + 1e-5f);
        }
        __syncthreads();
        const float mean = statv[0], rstd = statv[1];

        #pragma unroll
        for (int im = 0; im < 2; im++)
            #pragma unroll
            for (int hh = 0; hh < 2; hh++) {
                int r = wm*32 + im*16 + ly + hh*8;
                size_t rowoff = (((size_t)(b*CSZ + r))*TSZ + t)*FSZ;
                #pragma unroll
                for (int in = 0; in < 4; in++) {
                    int c = wn*32 + in*8 + lx*2;
                    float2 xr = *(const float2*)(x + rowoff + c);
                    float y0 = (acc[im][in][hh*2+0]-mean)*rstd*gp[r*FSZ+c]   + bep[r*FSZ+c]   + xr.x;
                    float y1 = (acc[im][in][hh*2+1]-mean)*rstd*gp[r*FSZ+c+1] + bep[r*FSZ+c+1] + xr.y;
                    *(float2*)(out + rowoff + c) = make_float2(y0, y1);
                }
            }
        __syncthreads();
    }
}

// ===========================================================================
// Softmax: fp32 logits in, fp16 P out
// ===========================================================================
__global__ void __launch_bounds__(256) softmax_kernel()
{
    const size_t row = blockIdx.x;
    const float4* p4 = reinterpret_cast<const float4*>(g_s) + row*256;
    const int tid = threadIdx.x, lane = tid & 31, warp = tid >> 5;
    __shared__ float sred[8];

    float4 v = p4[tid];
    float m = fmaxf(fmaxf(v.x, v.y), fmaxf(v.z, v.w));
    #pragma unroll
    for (int off = 16; off; off >>= 1) m = fmaxf(m, __shfl_xor_sync(0xffffffffu, m, off));
    if (lane == 0) sred[warp] = m;
    __syncthreads();
    float mm = sred[0];
    #pragma unroll
    for (int i = 1; i < 8; i++) mm = fmaxf(mm, sred[i]);
    __syncthreads();

    v.x = __expf(v.x - mm); v.y = __expf(v.y - mm);
    v.z = __expf(v.z - mm); v.w = __expf(v.w - mm);
    float s = v.x + v.y + v.z + v.w;
    #pragma unroll
    for (int off = 16; off; off >>= 1) s += __shfl_xor_sync(0xffffffffu, s, off);
    if (lane == 0) sred[warp] = s;
    __syncthreads();
    float ss = sred[0];
    #pragma unroll
    for (int i = 1; i < 8; i++) ss += sred[i];
    float inv = 1.0f/ss;

    __half2 h0 = __floats2half2_rn(v.x*inv, v.y*inv);
    __half2 h1 = __floats2half2_rn(v.z*inv, v.w*inv);
    __half2* o2 = reinterpret_cast<__half2*>(g_sh + row*TSZ);
    o2[tid*2]   = h0;
    o2[tid*2+1] = h1;
}

// ===========================================================================
extern "C" void kernel_launch(void* const* d_in, const int* in_sizes, int n_in,
                              void* d_out, int out_size)
{
    const float* x   = (const float*)d_in[0];
    const float* Wq  = (const float*)d_in[1];
    const float* bq  = (const float*)d_in[2];
    const float* aq  = (const float*)d_in[3];
    const float* gq  = (const float*)d_in[4];
    const float* beq = (const float*)d_in[5];
    const float* Wk  = (const float*)d_in[6];
    const float* bk  = (const float*)d_in[7];
    const float* ak  = (const float*)d_in[8];
    const float* gk  = (const float*)d_in[9];
    const float* bek = (const float*)d_in[10];
    const float* Wv  = (const float*)d_in[11];
    const float* bv  = (const float*)d_in[12];
    const float* av  = (const float*)d_in[13];
    const float* gv  = (const float*)d_in[14];
    const float* bev = (const float*)d_in[15];
    const float* Wp  = (const float*)d_in[16];
    const float* bp  = (const float*)d_in[17];
    const float* ap  = (const float*)d_in[18];
    const float* gp  = (const float*)d_in[19];
    const float* bep = (const float*)d_in[20];
    float* out = (float*)d_out;

    // One-time side-stream + fork/join events (host resources only; the
    // device work per call is identical and deterministic).
    static cudaStream_t s2 = nullptr;
    static cudaEvent_t evF = nullptr, evJ = nullptr;
    if (s2 == nullptr) {
        cudaStreamCreateWithFlags(&s2, cudaStreamNonBlocking);
        cudaEventCreateWithFlags(&evF, cudaEventDisableTiming);
        cudaEventCreateWithFlags(&evJ, cudaEventDisableTiming);
    }

    const int SMEM_QK = 2*QK_STAGE;    // 81920
    const int SMEM_PV = 3*PV_STAGE;    // 107520
    cudaFuncSetAttribute(qkv_qk_part, cudaFuncAttributeMaxDynamicSharedMemorySize, QKQ_SMEM);
    cudaFuncSetAttribute(qkv_v_part,  cudaFuncAttributeMaxDynamicSharedMemorySize, QV_SMEM);
    cudaFuncSetAttribute(proj_f16,    cudaFuncAttributeMaxDynamicSharedMemorySize, PJ_SMEM);
    cudaFuncSetAttribute(gemm_qk_f16, cudaFuncAttributeMaxDynamicSharedMemorySize, SMEM_QK);
    cudaFuncSetAttribute(gemm_pv_f16, cudaFuncAttributeMaxDynamicSharedMemorySize, SMEM_PV);

    // Fork: v-branch runs concurrently with q/k branch + QK gemm + softmax.
    cudaEventRecord(evF, 0);
    cudaStreamWaitEvent(s2, evF, 0);
    qkv_v_part<<<BSZ*TSZ/2, 256, QV_SMEM, s2>>>(x, Wv, bv, av, gv, bev);

    qkv_qk_part<<<BSZ*TSZ/2, 256, QKQ_SMEM>>>(x, Wq, bq, aq, gq, beq,
                                              Wk, bk, ak, gk, bek);
    gemm_qk_f16<<<dim3(8, 8, NB), 256, SMEM_QK>>>();
    softmax_kernel<<<NB*TSZ, 256>>>();

    // Join: PV needs v.
    cudaEventRecord(evJ, s2);
    cudaStreamWaitEvent(0, evJ, 0);
    gemm_pv_f16<<<dim3(16, 8, NB), 256, SMEM_PV>>>();
    proj_f16<<<BSZ*TSZ/2, 256, PJ_SMEM>>>(x, Wp, bp, ap, gp, bep, out);
}

// round 13
// speedup vs baseline: 1.0305x; 1.0305x over previous
#include <cuda_runtime.h>
#include <cuda_fp16.h>
#include <cstdint>

// Problem constants
#define BSZ 4
#define CSZ 64
#define TSZ 1024
#define FSZ 128
#define HN  4
#define HIDN 4
#define CHN 16
#define NB  (HN*BSZ)      // 16 attention batches
#define DQK (HIDN*FSZ)    // 512
#define DV  (CHN*FSZ)     // 2048

// Scratch (device globals: allocation-free rule)
__device__ __half g_qh[(size_t)NB*TSZ*DQK];          // q hi (fp16)
__device__ __half g_ql[(size_t)NB*TSZ*DQK];          // q lo
__device__ __half g_kh[(size_t)NB*TSZ*DQK];          // k hi
__device__ __half g_kl[(size_t)NB*TSZ*DQK];          // k lo
__device__ __half g_vh[(size_t)NB*TSZ*DV];           // v fp16 [n][t][d]
__device__ float  g_s [(size_t)NB*TSZ*TSZ];          // logits fp32
__device__ __half g_sh[(size_t)NB*TSZ*TSZ];          // P fp16 [n][t][t']
__device__ __half g_aoh[(size_t)BSZ*CSZ*TSZ*FSZ];    // attention out, fp16

// ===========================================================================
// helpers
// ===========================================================================
__device__ __forceinline__ uint32_t smem_u32(const void* p) {
    uint32_t a;
    asm("{ .reg .u64 t; cvta.to.shared.u64 t, %1; cvt.u32.u64 %0, t; }" : "=r"(a) : "l"(p));
    return a;
}
__device__ __forceinline__ void ldsm4(uint32_t& r0, uint32_t& r1, uint32_t& r2, uint32_t& r3,
                                      uint32_t addr) {
    asm volatile("ldmatrix.sync.aligned.m8n8.x4.shared.b16 {%0,%1,%2,%3}, [%4];"
                 : "=r"(r0), "=r"(r1), "=r"(r2), "=r"(r3) : "r"(addr));
}
__device__ __forceinline__ void ldsm4t(uint32_t& r0, uint32_t& r1, uint32_t& r2, uint32_t& r3,
                                       uint32_t addr) {
    asm volatile("ldmatrix.sync.aligned.m8n8.x4.trans.shared.b16 {%0,%1,%2,%3}, [%4];"
                 : "=r"(r0), "=r"(r1), "=r"(r2), "=r"(r3) : "r"(addr));
}
// fp16 m16n8k16, fp32 accumulate
__device__ __forceinline__ void mma16(float* d, const uint32_t* a, uint32_t b0, uint32_t b1) {
    asm volatile("mma.sync.aligned.m16n8k16.row.col.f32.f16.f16.f32 "
                 "{%0,%1,%2,%3}, {%4,%5,%6,%7}, {%8,%9}, {%0,%1,%2,%3};"
                 : "+f"(d[0]), "+f"(d[1]), "+f"(d[2]), "+f"(d[3])
                 : "r"(a[0]), "r"(a[1]), "r"(a[2]), "r"(a[3]), "r"(b0), "r"(b1));
}
__device__ __forceinline__ void cp16(uint32_t dst, const void* src) {
    asm volatile("cp.async.cg.shared.global [%0], [%1], 16;" :: "r"(dst), "l"(src));
}
#define CP_COMMIT() asm volatile("cp.async.commit_group;" ::: "memory")
#define CP_WAIT0()  asm volatile("cp.async.wait_group 0;"  ::: "memory")
#define CP_WAIT1()  asm volatile("cp.async.wait_group 1;"  ::: "memory")

// fp16 hi/lo split of a float4 -> two packed uint2 (4 halves each)
__device__ __forceinline__ void split4(float4 v, uint2& hh, uint2& ll) {
    __half h0 = __float2half_rn(v.x), h1 = __float2half_rn(v.y);
    __half h2 = __float2half_rn(v.z), h3 = __float2half_rn(v.w);
    __half l0 = __float2half_rn(v.x - __half2float(h0));
    __half l1 = __float2half_rn(v.y - __half2float(h1));
    __half l2 = __float2half_rn(v.z - __half2float(h2));
    __half l3 = __float2half_rn(v.w - __half2float(h3));
    __half2 a = __halves2half2(h0, h1), b = __halves2half2(h2, h3);
    __half2 c = __halves2half2(l0, l1), d = __halves2half2(l2, l3);
    hh.x = *(uint32_t*)&a; hh.y = *(uint32_t*)&b;
    ll.x = *(uint32_t*)&c; ll.y = *(uint32_t*)&d;
}

// ===========================================================================
// GEMM 1: S = scale * Q K^T  (3xFP16 split, NT, 128x128, k-chunks of 32)
// ===========================================================================
#define QKC 32
#define QK_NCH (DQK/QKC)           // 16
#define A_PITCH 80                 // 64B data + 16B pad
#define QK_TILE (128*A_PITCH)      // 10240 B
#define QK_STAGE (4*QK_TILE)       // 40960 B

__global__ void __launch_bounds__(256, 2) gemm_qk_f16()
{
    extern __shared__ char smq[];
    const int tid = threadIdx.x, lane = tid & 31, warp = tid >> 5;
    const int wm = warp >> 2, wn = warp & 3;
    const int bz = blockIdx.z, m0 = blockIdx.y*128, n0 = blockIdx.x*128;
    const __half* Ah = g_qh + ((size_t)bz*TSZ + m0)*DQK;
    const __half* Al = g_ql + ((size_t)bz*TSZ + m0)*DQK;
    const __half* Bh = g_kh + ((size_t)bz*TSZ + n0)*DQK;
    const __half* Bl = g_kl + ((size_t)bz*TSZ + n0)*DQK;

    float acc[4][4][4];
    #pragma unroll
    for (int i = 0; i < 4; i++)
        #pragma unroll
        for (int j = 0; j < 4; j++)
            #pragma unroll
            for (int k = 0; k < 4; k++) acc[i][j][k] = 0.f;

    const uint32_t sbase = smem_u32(smq);
    const uint32_t aoff = (wm*64 + (lane & 15))*A_PITCH + (lane >> 4)*16;
    const uint32_t boff = (wn*32 + (lane & 7))*A_PITCH + (lane >> 3)*16;

    auto issue = [&](int c, int s) {
        uint32_t dst = sbase + s*QK_STAGE;
        #pragma unroll
        for (int i = 0; i < 2; i++) {
            int idx = tid + 256*i;
            int row = idx >> 2, seg = idx & 3;
            uint32_t d = row*A_PITCH + seg*16;
            size_t sa = (size_t)row*(DQK*2) + (size_t)c*(QKC*2) + seg*16;
            cp16(dst + d,             (const char*)Ah + sa);
            cp16(dst + QK_TILE + d,   (const char*)Al + sa);
            cp16(dst + 2*QK_TILE + d, (const char*)Bh + sa);
            cp16(dst + 3*QK_TILE + d, (const char*)Bl + sa);
        }
        CP_COMMIT();
    };

    issue(0, 0);
    for (int c = 0; c < QK_NCH; c++) {
        CP_WAIT0();
        __syncthreads();
        if (c + 1 < QK_NCH) issue(c+1, (c+1) & 1);
        const uint32_t so = sbase + (c & 1)*QK_STAGE;

        uint32_t bh[4][4], bl[4][4];
        #pragma unroll
        for (int in = 0; in < 4; in++) {
            ldsm4(bh[in][0], bh[in][1], bh[in][2], bh[in][3],
                  so + 2*QK_TILE + boff + in*(8*A_PITCH));
            ldsm4(bl[in][0], bl[in][1], bl[in][2], bl[in][3],
                  so + 3*QK_TILE + boff + in*(8*A_PITCH));
        }
        #pragma unroll
        for (int ks = 0; ks < 2; ks++) {
            uint32_t ah[4][4], al[4][4];
            #pragma unroll
            for (int im = 0; im < 4; im++) {
                ldsm4(ah[im][0], ah[im][1], ah[im][2], ah[im][3],
                      so + aoff + im*(16*A_PITCH) + ks*32);
                ldsm4(al[im][0], al[im][1], al[im][2], al[im][3],
                      so + QK_TILE + aoff + im*(16*A_PITCH) + ks*32);
            }
            #pragma unroll
            for (int im = 0; im < 4; im++)
                #pragma unroll
                for (int in = 0; in < 4; in++) {
                    mma16(acc[im][in], ah[im], bh[in][2*ks], bh[in][2*ks+1]);
                    mma16(acc[im][in], ah[im], bl[in][2*ks], bl[in][2*ks+1]);
                    mma16(acc[im][in], al[im], bh[in][2*ks], bh[in][2*ks+1]);
                }
        }
    }

    const float scale = 0.0441941738241592f;   // 1/sqrt(512)
    float* Cb = g_s + (size_t)bz*TSZ*TSZ;
    const int mbase = m0 + wm*64, nbase = n0 + wn*32;
    #pragma unroll
    for (int im = 0; im < 4; im++)
        #pragma unroll
        for (int in = 0; in < 4; in++) {
            int rr = mbase + im*16 + (lane >> 2);
            int cc = nbase + in*8 + (lane & 3)*2;
            float2 o0 = make_float2(acc[im][in][0]*scale, acc[im][in][1]*scale);
            float2 o1 = make_float2(acc[im][in][2]*scale, acc[im][in][3]*scale);
            *(float2*)(Cb + (size_t)rr*TSZ + cc)     = o0;
            *(float2*)(Cb + (size_t)(rr+8)*TSZ + cc) = o1;
        }
}

// ===========================================================================
// GEMM 2: O = P V  (single FP16; V via ldmatrix.trans; K-chunk 64; 3-stage)
//   Epilogue writes fp16 AO directly (g_aoh).
// ===========================================================================
#define PVC 64
#define PV_NCH (TSZ/PVC)           // 16
#define PVA_PITCH 144
#define PVB_PITCH 272
#define PVA_TILE (128*PVA_PITCH)   // 18432
#define PVB_TILE (64*PVB_PITCH)    // 17408
#define PV_STAGE (PVA_TILE + PVB_TILE)  // 35840

__global__ void __launch_bounds__(256, 2) gemm_pv_f16()
{
    extern __shared__ char smp[];
    const int tid = threadIdx.x, lane = tid & 31, warp = tid >> 5;
    const int wm = warp >> 2, wn = warp & 3;
    const int bz = blockIdx.z, m0 = blockIdx.y*128, n0 = blockIdx.x*128;
    const __half* A = g_sh + (size_t)bz*TSZ*TSZ + (size_t)m0*TSZ;
    const __half* B = g_vh + (size_t)bz*TSZ*DV;

    float acc[4][4][4];
    #pragma unroll
    for (int i = 0; i < 4; i++)
        #pragma unroll
        for (int j = 0; j < 4; j++)
            #pragma unroll
            for (int k = 0; k < 4; k++) acc[i][j][k] = 0.f;

    const uint32_t sbase = smem_u32(smp);
    const uint32_t aoff = (wm*64 + (lane & 15))*PVA_PITCH + (lane >> 4)*16;
    const uint32_t btoff = PVA_TILE + lane*PVB_PITCH + wn*64;

    auto issue = [&](int c, int s) {
        uint32_t dst = sbase + s*PV_STAGE;
        #pragma unroll
        for (int i = 0; i < 4; i++) {
            int idx = tid + 256*i;
            int ar = idx >> 3, as = idx & 7;
            cp16(dst + ar*PVA_PITCH + as*16,
                 (const char*)A + (size_t)ar*(TSZ*2) + (size_t)c*(PVC*2) + as*16);
            int br = idx >> 4, bs = idx & 15;
            cp16(dst + PVA_TILE + br*PVB_PITCH + bs*16,
                 (const char*)B + ((size_t)(c*PVC + br))*(DV*2) + (size_t)n0*2 + bs*16);
        }
        CP_COMMIT();
    };

    issue(0, 0);
    issue(1, 1);
    for (int c = 0; c < PV_NCH; c++) {
        if (c + 1 < PV_NCH) CP_WAIT1();
        else                CP_WAIT0();
        __syncthreads();
        if (c + 2 < PV_NCH) issue(c+2, (c+2) % 3);
        const uint32_t so = sbase + (c % 3)*PV_STAGE;

        #pragma unroll
        for (int half = 0; half < 2; half++) {
            uint32_t bt[4][4];
            #pragma unroll
            for (int in = 0; in < 4; in++)
                ldsm4t(bt[in][0], bt[in][1], bt[in][2], bt[in][3],
                       so + btoff + half*(32*PVB_PITCH) + in*16);
            #pragma unroll
            for (int ks = 0; ks < 2; ks++) {
                uint32_t a[4][4];
                #pragma unroll
                for (int im = 0; im < 4; im++)
                    ldsm4(a[im][0], a[im][1], a[im][2], a[im][3],
                          so + aoff + im*(16*PVA_PITCH) + (half*2 + ks)*32);
                #pragma unroll
                for (int im = 0; im < 4; im++)
                    #pragma unroll
                    for (int in = 0; in < 4; in++)
                        mma16(acc[im][in], a[im], bt[in][2*ks], bt[in][2*ks+1]);
            }
        }
    }

    const int h = bz >> 2, bb = bz & 3;
    const int cc_ch = h*CHN + blockIdx.x;
    const int mbase = m0 + wm*64, nbase = wn*32;
    __half* Ob = g_aoh + ((size_t)(bb*CSZ + cc_ch)*TSZ)*FSZ;
    #pragma unroll
    for (int im = 0; im < 4; im++)
        #pragma unroll
        for (int in = 0; in < 4; in++) {
            int rr = mbase + im*16 + (lane >> 2);
            int ff = nbase + in*8 + (lane & 3)*2;
            *(__half2*)(Ob + (size_t)rr*FSZ + ff) =
                __floats2half2_rn(acc[im][in][0], acc[im][in][1]);
            *(__half2*)(Ob + (size_t)(rr+8)*FSZ + ff) =
                __floats2half2_rn(acc[im][in][2], acc[im][in][3]);
        }
}

// ===========================================================================
// QKV: per block handles TWO t's. Y[96,128] = Wall[96,64] @ X[64,128] per t.
//   3xFP16 m16n8k16; W converted once, two compute phases.
// ===========================================================================
#define QW_PITCH 144               // 128B (64 halves) + 16 pad
#define QX_PITCH 272               // 256B (128 halves) + 16 pad
#define QX_T (64*QX_PITCH)         // one t's X tile: 17408
#define QKV_WH 0
#define QKV_WL (96*QW_PITCH)                 // 13824
#define QKV_XH (2*96*QW_PITCH)               // 27648
#define QKV_XSZ (2*QX_T)                     // 34816 (2 t's)
#define QKV_XL (QKV_XH + QKV_XSZ)            // 62464
#define QKV_SMEM (QKV_XH + 2*QKV_XSZ)        // 97280

__global__ void __launch_bounds__(256) qkv_f16(
    const float* __restrict__ x,
    const float* __restrict__ Wq, const float* __restrict__ bq,
    const float* __restrict__ aq, const float* __restrict__ gq, const float* __restrict__ beq,
    const float* __restrict__ Wk, const float* __restrict__ bk,
    const float* __restrict__ ak, const float* __restrict__ gk, const float* __restrict__ bek,
    const float* __restrict__ Wv, const float* __restrict__ bv,
    const float* __restrict__ av, const float* __restrict__ gv, const float* __restrict__ bev)
{
    extern __shared__ char sm[];
    __shared__ float rowred[96*2];
    __shared__ float stats[12*2];
    __shared__ float biasS[96], alphS[96];

    const int tid = threadIdx.x, lane = tid & 31, warp = tid >> 5;
    const int wm = warp >> 2, wn = warp & 3;
    const int ly = lane >> 2, lx = lane & 3;
    const int b = blockIdx.x >> 9, t0 = (blockIdx.x & 511)*2;

    if (tid < 96) {
        if (tid < 16)      { biasS[tid] = bq[tid];    alphS[tid] = aq[tid>>2]; }
        else if (tid < 32) { biasS[tid] = bk[tid-16]; alphS[tid] = ak[(tid-16)>>2]; }
        else               { biasS[tid] = bv[tid-32]; alphS[tid] = av[(tid-32)>>4]; }
    }

    // W: 96 rows x 64 floats -> fp16 hi/lo (converted ONCE for both t's)
    #pragma unroll
    for (int j = 0; j < 6; j++) {
        int idx = tid + 256*j;
        int row = idx >> 4, c4 = idx & 15;
        const float* src;
        if (row < 16)      src = Wq + row*CSZ;
        else if (row < 32) src = Wk + (row-16)*CSZ;
        else               src = Wv + (row-32)*CSZ;
        float4 w = *(const float4*)(src + c4*4);
        uint2 hh, ll; split4(w, hh, ll);
        *(uint2*)(sm + QKV_WH + row*QW_PITCH + c4*8) = hh;
        *(uint2*)(sm + QKV_WL + row*QW_PITCH + c4*8) = ll;
    }
    // X: both t's: 2 x 64 c-rows x 128 f (4096 float4, 16/thread)
    #pragma unroll
    for (int j = 0; j < 16; j++) {
        int idx = tid + 256*j;
        int tt = idx >> 11, rem = idx & 2047;
        int c = rem >> 5, f4 = rem & 31;
        float4 v = *(const float4*)(x + (((size_t)(b*CSZ + c))*TSZ + t0 + tt)*FSZ + f4*4);
        uint2 hh, ll; split4(v, hh, ll);
        *(uint2*)(sm + QKV_XH + tt*QX_T + c*QX_PITCH + f4*8) = hh;
        *(uint2*)(sm + QKV_XL + tt*QX_T + c*QX_PITCH + f4*8) = ll;
    }
    __syncthreads();

    const uint32_t sbase = smem_u32(sm);
    const uint32_t awoff = sbase + QKV_WH + (wm*48 + (lane & 15))*QW_PITCH + (lane >> 4)*16;

    for (int tt = 0; tt < 2; tt++) {
        const int t = t0 + tt;
        if (tid < 192) rowred[tid] = 0.f;
        __syncthreads();

        const uint32_t bxoff = sbase + QKV_XH + tt*QX_T + lane*QX_PITCH + wn*64;

        float acc[3][4][4];
        #pragma unroll
        for (int i = 0; i < 3; i++)
            #pragma unroll
            for (int j = 0; j < 4; j++)
                #pragma unroll
                for (int k = 0; k < 4; k++) acc[i][j][k] = 0.f;

        #pragma unroll
        for (int half = 0; half < 2; half++) {
            uint32_t bth[4][4], btl[4][4];
            #pragma unroll
            for (int in = 0; in < 4; in++) {
                ldsm4t(bth[in][0], bth[in][1], bth[in][2], bth[in][3],
                       bxoff + half*(32*QX_PITCH) + in*16);
                ldsm4t(btl[in][0], btl[in][1], btl[in][2], btl[in][3],
                       bxoff + QKV_XSZ + half*(32*QX_PITCH) + in*16);
            }
            #pragma unroll
            for (int ks = 0; ks < 2; ks++) {
                const int kstep = half*2 + ks;
                uint32_t ah[3][4], al[3][4];
                #pragma unroll
                for (int im = 0; im < 3; im++) {
                    ldsm4(ah[im][0], ah[im][1], ah[im][2], ah[im][3],
                          awoff + im*(16*QW_PITCH) + kstep*32);
                    ldsm4(al[im][0], al[im][1], al[im][2], al[im][3],
                          awoff + (QKV_WL - QKV_WH) + im*(16*QW_PITCH) + kstep*32);
                }
                #pragma unroll
                for (int im = 0; im < 3; im++)
                    #pragma unroll
                    for (int in = 0; in < 4; in++) {
                        mma16(acc[im][in], ah[im], bth[in][2*ks], bth[in][2*ks+1]);
                        mma16(acc[im][in], ah[im], btl[in][2*ks], btl[in][2*ks+1]);
                        mma16(acc[im][in], al[im], bth[in][2*ks], bth[in][2*ks+1]);
                    }
            }
        }

        // bias + PReLU + per-row partial sums
        float rs[3][2], rq[3][2];
        #pragma unroll
        for (int im = 0; im < 3; im++) { rs[im][0]=rs[im][1]=0.f; rq[im][0]=rq[im][1]=0.f; }
        #pragma unroll
        for (int im = 0; im < 3; im++)
            #pragma unroll
            for (int hh = 0; hh < 2; hh++) {
                int r = wm*48 + im*16 + ly + hh*8;
                float bi = biasS[r], alp = alphS[r];
                #pragma unroll
                for (int in = 0; in < 4; in++)
                    #pragma unroll
                    for (int e = 0; e < 2; e++) {
                        float y = acc[im][in][hh*2+e] + bi;
                        y = y > 0.f ? y : alp*y;
                        acc[im][in][hh*2+e] = y;
                        rs[im][hh] += y; rq[im][hh] += y*y;
                    }
            }
        #pragma unroll
        for (int im = 0; im < 3; im++)
            #pragma unroll
            for (int hh = 0; hh < 2; hh++) {
                float s = rs[im][hh], q = rq[im][hh];
                s += __shfl_xor_sync(0xffffffffu, s, 1); q += __shfl_xor_sync(0xffffffffu, q, 1);
                s += __shfl_xor_sync(0xffffffffu, s, 2); q += __shfl_xor_sync(0xffffffffu, q, 2);
                if (lx == 0) {
                    int r = wm*48 + im*16 + ly + hh*8;
                    atomicAdd(&rowred[2*r], s); atomicAdd(&rowred[2*r+1], q);
                }
            }
        __syncthreads();
        if (tid < 12) {
            int st, cnt;
            if (tid < 8) { st = tid*4; cnt = 4; } else { st = 32 + (tid-8)*16; cnt = 16; }
            float s = 0.f, q = 0.f;
            for (int r = st; r < st+cnt; r++) { s += rowred[2*r]; q += rowred[2*r+1]; }
            float inv = 1.f/(cnt*FSZ);
            float mean = s*inv, var = q*inv - mean*mean;
            stats[2*tid] = mean; stats[2*tid+1] = rsqrtf(var + 1e-5f);
        }
        __syncthreads();

        // normalize + store (q/k fp16 hi/lo; v fp16)
        #pragma unroll
        for (int im = 0; im < 3; im++)
            #pragma unroll
            for (int hh = 0; hh < 2; hh++) {
                int r = wm*48 + im*16 + ly + hh*8;
                int grp = (r < 32) ? (r >> 2) : ((r >> 4) + 6);
                float mean = stats[2*grp], rstd = stats[2*grp+1];
                if (r < 32) {
                    int jrow = (r < 16) ? r : r - 16;
                    const float* gvec  = (r < 16) ? gq  : gk;
                    const float* bevec = (r < 16) ? beq : bek;
                    size_t off = (((size_t)((jrow>>2)*BSZ + b)*TSZ + t)*DQK) + (jrow&3)*FSZ;
                    __half* dh = (r < 16) ? (g_qh + off) : (g_kh + off);
                    __half* dl = (r < 16) ? (g_ql + off) : (g_kl + off);
                    #pragma unroll
                    for (int in = 0; in < 4; in++) {
                        int c = wn*32 + in*8 + lx*2;
                        float y0 = (acc[im][in][hh*2+0]-mean)*rstd*gvec[jrow*FSZ+c]   + bevec[jrow*FSZ+c];
                        float y1 = (acc[im][in][hh*2+1]-mean)*rstd*gvec[jrow*FSZ+c+1] + bevec[jrow*FSZ+c+1];
                        __half h0 = __float2half_rn(y0), h1 = __float2half_rn(y1);
                        __half l0 = __float2half_rn(y0 - __half2float(h0));
                        __half l1 = __float2half_rn(y1 - __half2float(h1));
                        *(__half2*)(dh + c) = __halves2half2(h0, h1);
                        *(__half2*)(dl + c) = __halves2half2(l0, l1);
                    }
                } else {
                    int jrow = r - 32;
                    __half* dst = g_vh + (((size_t)((jrow>>4)*BSZ + b)*TSZ + t)*DV) + (jrow&15)*FSZ;
                    #pragma unroll
                    for (int in = 0; in < 4; in++) {
                        int c = wn*32 + in*8 + lx*2;
                        float y0 = (acc[im][in][hh*2+0]-mean)*rstd*gv[jrow*FSZ+c]   + bev[jrow*FSZ+c];
                        float y1 = (acc[im][in][hh*2+1]-mean)*rstd*gv[jrow*FSZ+c+1] + bev[jrow*FSZ+c+1];
                        *(__half2*)(dst + c) = __floats2half2_rn(y0, y1);
                    }
                }
            }
        __syncthreads();
    }
}

// ===========================================================================
// PROJ: per block FOUR t's. Y[64,128] = Wp[64,64] @ AO[64,128] per t.
//   AO is fp16 (g_aoh) -> X loaded raw via cp.async; 2-term split (W only).
// ===========================================================================
#define PJX_PITCH 272
#define PJX_T (64*PJX_PITCH)                 // 17408
#define PJ_WH 0
#define PJ_WL (64*QW_PITCH)                  // 9216
#define PJ_X  (2*64*QW_PITCH)                // 18432
#define PJ_SMEM (PJ_X + 4*PJX_T)             // 88064

__global__ void __launch_bounds__(256) proj_f16(
    const float* __restrict__ x, const float* __restrict__ Wp,
    const float* __restrict__ bp, const float* __restrict__ ap,
    const float* __restrict__ gp, const float* __restrict__ bep,
    float* __restrict__ out)
{
    extern __shared__ char sm[];
    __shared__ float red[2];
    __shared__ float statv[2];

    const int tid = threadIdx.x, lane = tid & 31, warp = tid >> 5;
    const int wm = warp >> 2, wn = warp & 3;
    const int ly = lane >> 2, lx = lane & 3;
    const int b = blockIdx.x >> 8, t0 = (blockIdx.x & 255)*4;

    const uint32_t sbase = smem_u32(sm);

    // X = AO (fp16): raw cp.async, four t's. 4096 x 16B segs, 16/thread.
    #pragma unroll
    for (int j = 0; j < 16; j++) {
        int idx = tid + 256*j;
        int tt = idx >> 10, rem = idx & 1023;
        int c = rem >> 4, seg = rem & 15;
        cp16(sbase + PJ_X + tt*PJX_T + c*PJX_PITCH + seg*16,
             (const char*)(g_aoh + (((size_t)(b*CSZ + c))*TSZ + t0 + tt)*FSZ) + seg*16);
    }
    CP_COMMIT();

    // W: 64 rows x 64 floats (converted ONCE for all four t's, hi/lo)
    #pragma unroll
    for (int j = 0; j < 4; j++) {
        int idx = tid + 256*j;
        int row = idx >> 4, c4 = idx & 15;
        float4 w = *(const float4*)(Wp + row*CSZ + c4*4);
        uint2 hh, ll; split4(w, hh, ll);
        *(uint2*)(sm + PJ_WH + row*QW_PITCH + c4*8) = hh;
        *(uint2*)(sm + PJ_WL + row*QW_PITCH + c4*8) = ll;
    }
    CP_WAIT0();
    __syncthreads();

    const uint32_t awoff = sbase + PJ_WH + (wm*32 + (lane & 15))*QW_PITCH + (lane >> 4)*16;

    for (int tt = 0; tt < 4; tt++) {
        const int t = t0 + tt;
        if (tid < 2) red[tid] = 0.f;
        __syncthreads();

        const uint32_t bxoff = sbase + PJ_X + tt*PJX_T + lane*PJX_PITCH + wn*64;

        float acc[2][4][4];
        #pragma unroll
        for (int i = 0; i < 2; i++)
            #pragma unroll
            for (int j = 0; j < 4; j++)
                #pragma unroll
                for (int k = 0; k < 4; k++) acc[i][j][k] = 0.f;

        #pragma unroll
        for (int half = 0; half < 2; half++) {
            uint32_t bt[4][4];
            #pragma unroll
            for (int in = 0; in < 4; in++)
                ldsm4t(bt[in][0], bt[in][1], bt[in][2], bt[in][3],
                       bxoff + half*(32*PJX_PITCH) + in*16);
            #pragma unroll
            for (int ks = 0; ks < 2; ks++) {
                const int kstep = half*2 + ks;
                uint32_t ah[2][4], al[2][4];
                #pragma unroll
                for (int im = 0; im < 2; im++) {
                    ldsm4(ah[im][0], ah[im][1], ah[im][2], ah[im][3],
                          awoff + im*(16*QW_PITCH) + kstep*32);
                    ldsm4(al[im][0], al[im][1], al[im][2], al[im][3],
                          awoff + (PJ_WL - PJ_WH) + im*(16*QW_PITCH) + kstep*32);
                }
                #pragma unroll
                for (int im = 0; im < 2; im++)
                    #pragma unroll
                    for (int in = 0; in < 4; in++) {
                        mma16(acc[im][in], ah[im], bt[in][2*ks], bt[in][2*ks+1]);
                        mma16(acc[im][in], al[im], bt[in][2*ks], bt[in][2*ks+1]);
                    }
            }
        }

        const float alp = ap[0];
        float s1 = 0.f, s2 = 0.f;
        #pragma unroll
        for (int im = 0; im < 2; im++)
            #pragma unroll
            for (int hh = 0; hh < 2; hh++) {
                int r = wm*32 + im*16 + ly + hh*8;
                float bi = bp[r];
                #pragma unroll
                for (int in = 0; in < 4; in++)
                    #pragma unroll
                    for (int e = 0; e < 2; e++) {
                        float y = acc[im][in][hh*2+e] + bi;
                        y = y > 0.f ? y : alp*y;
                        acc[im][in][hh*2+e] = y;
                        s1 += y; s2 += y*y;
                    }
            }
        #pragma unroll
        for (int off = 16; off; off >>= 1) {
            s1 += __shfl_xor_sync(0xffffffffu, s1, off);
            s2 += __shfl_xor_sync(0xffffffffu, s2, off);
        }
        if (lane == 0) { atomicAdd(&red[0], s1); atomicAdd(&red[1], s2); }
        __syncthreads();
        if (tid == 0) {
            const float invn = 1.f/(CSZ*FSZ);
            float mean = red[0]*invn, var = red[1]*invn - mean*mean;
            statv[0] = mean; statv[1] = rsqrtf(var + 1e-5f);
        }
        __syncthreads();
        const float mean = statv[0], rstd = statv[1];

        #pragma unroll
        for (int im = 0; im < 2; im++)
            #pragma unroll
            for (int hh = 0; hh < 2; hh++) {
                int r = wm*32 + im*16 + ly + hh*8;
                size_t rowoff = (((size_t)(b*CSZ + r))*TSZ + t)*FSZ;
                #pragma unroll
                for (int in = 0; in < 4; in++) {
                    int c = wn*32 + in*8 + lx*2;
                    float2 xr = *(const float2*)(x + rowoff + c);
                    float y0 = (acc[im][in][hh*2+0]-mean)*rstd*gp[r*FSZ+c]   + bep[r*FSZ+c]   + xr.x;
                    float y1 = (acc[im][in][hh*2+1]-mean)*rstd*gp[r*FSZ+c+1] + bep[r*FSZ+c+1] + xr.y;
                    *(float2*)(out + rowoff + c) = make_float2(y0, y1);
                }
            }
        __syncthreads();
    }
}

// ===========================================================================
// Softmax: fp32 logits in, fp16 P out
// ===========================================================================
__global__ void __launch_bounds__(256) softmax_kernel()
{
    const size_t row = blockIdx.x;
    const float4* p4 = reinterpret_cast<const float4*>(g_s) + row*256;
    const int tid = threadIdx.x, lane = tid & 31, warp = tid >> 5;
    __shared__ float sred[8];

    float4 v = p4[tid];
    float m = fmaxf(fmaxf(v.x, v.y), fmaxf(v.z, v.w));
    #pragma unroll
    for (int off = 16; off; off >>= 1) m = fmaxf(m, __shfl_xor_sync(0xffffffffu, m, off));
    if (lane == 0) sred[warp] = m;
    __syncthreads();
    float mm = sred[0];
    #pragma unroll
    for (int i = 1; i < 8; i++) mm = fmaxf(mm, sred[i]);
    __syncthreads();

    v.x = __expf(v.x - mm); v.y = __expf(v.y - mm);
    v.z = __expf(v.z - mm); v.w = __expf(v.w - mm);
    float s = v.x + v.y + v.z + v.w;
    #pragma unroll
    for (int off = 16; off; off >>= 1) s += __shfl_xor_sync(0xffffffffu, s, off);
    if (lane == 0) sred[warp] = s;
    __syncthreads();
    float ss = sred[0];
    #pragma unroll
    for (int i = 1; i < 8; i++) ss += sred[i];
    float inv = 1.0f/ss;

    __half2 h0 = __floats2half2_rn(v.x*inv, v.y*inv);
    __half2 h1 = __floats2half2_rn(v.z*inv, v.w*inv);
    __half2* o2 = reinterpret_cast<__half2*>(g_sh + row*TSZ);
    o2[tid*2]   = h0;
    o2[tid*2+1] = h1;
}

// ===========================================================================
extern "C" void kernel_launch(void* const* d_in, const int* in_sizes, int n_in,
                              void* d_out, int out_size)
{
    const float* x   = (const float*)d_in[0];
    const float* Wq  = (const float*)d_in[1];
    const float* bq  = (const float*)d_in[2];
    const float* aq  = (const float*)d_in[3];
    const float* gq  = (const float*)d_in[4];
    const float* beq = (const float*)d_in[5];
    const float* Wk  = (const float*)d_in[6];
    const float* bk  = (const float*)d_in[7];
    const float* ak  = (const float*)d_in[8];
    const float* gk  = (const float*)d_in[9];
    const float* bek = (const float*)d_in[10];
    const float* Wv  = (const float*)d_in[11];
    const float* bv  = (const float*)d_in[12];
    const float* av  = (const float*)d_in[13];
    const float* gv  = (const float*)d_in[14];
    const float* bev = (const float*)d_in[15];
    const float* Wp  = (const float*)d_in[16];
    const float* bp  = (const float*)d_in[17];
    const float* ap  = (const float*)d_in[18];
    const float* gp  = (const float*)d_in[19];
    const float* bep = (const float*)d_in[20];
    float* out = (float*)d_out;

    const int SMEM_QK = 2*QK_STAGE;    // 81920
    const int SMEM_PV = 3*PV_STAGE;    // 107520
    cudaFuncSetAttribute(qkv_f16,     cudaFuncAttributeMaxDynamicSharedMemorySize, QKV_SMEM);
    cudaFuncSetAttribute(proj_f16,    cudaFuncAttributeMaxDynamicSharedMemorySize, PJ_SMEM);
    cudaFuncSetAttribute(gemm_qk_f16, cudaFuncAttributeMaxDynamicSharedMemorySize, SMEM_QK);
    cudaFuncSetAttribute(gemm_pv_f16, cudaFuncAttributeMaxDynamicSharedMemorySize, SMEM_PV);

    qkv_f16<<<BSZ*TSZ/2, 256, QKV_SMEM>>>(x, Wq, bq, aq, gq, beq,
                                          Wk, bk, ak, gk, bek,
                                          Wv, bv, av, gv, bev);
    gemm_qk_f16<<<dim3(8, 8, NB), 256, SMEM_QK>>>();
    softmax_kernel<<<NB*TSZ, 256>>>();
    gemm_pv_f16<<<dim3(16, 8, NB), 256, SMEM_PV>>>();
    proj_f16<<<BSZ*TSZ/4, 256, PJ_SMEM>>>(x, Wp, bp, ap, gp, bep, out);
}

// round 14
// speedup vs baseline: 1.1344x; 1.1008x over previous
#include <cuda_runtime.h>
#include <cuda_fp16.h>
#include <cstdint>

// Problem constants
#define BSZ 4
#define CSZ 64
#define TSZ 1024
#define FSZ 128
#define HN  4
#define HIDN 4
#define CHN 16
#define NB  (HN*BSZ)      // 16 attention batches
#define DQK (HIDN*FSZ)    // 512
#define DV  (CHN*FSZ)     // 2048

// Scratch (device globals: allocation-free rule)
__device__ __half g_qh[(size_t)NB*TSZ*DQK];          // q hi (fp16)
__device__ __half g_ql[(size_t)NB*TSZ*DQK];          // q lo
__device__ __half g_kh[(size_t)NB*TSZ*DQK];          // k (fp16, single)
__device__ __half g_vh[(size_t)NB*TSZ*DV];           // v fp16 [n][t][d]
__device__ float  g_s [(size_t)NB*TSZ*TSZ];          // logits fp32
__device__ __half g_sh[(size_t)NB*TSZ*TSZ];          // P fp16 [n][t][t']
__device__ __half g_aoh[(size_t)BSZ*CSZ*TSZ*FSZ];    // attention out, fp16

// ===========================================================================
// helpers
// ===========================================================================
__device__ __forceinline__ uint32_t smem_u32(const void* p) {
    uint32_t a;
    asm("{ .reg .u64 t; cvta.to.shared.u64 t, %1; cvt.u32.u64 %0, t; }" : "=r"(a) : "l"(p));
    return a;
}
__device__ __forceinline__ void ldsm4(uint32_t& r0, uint32_t& r1, uint32_t& r2, uint32_t& r3,
                                      uint32_t addr) {
    asm volatile("ldmatrix.sync.aligned.m8n8.x4.shared.b16 {%0,%1,%2,%3}, [%4];"
                 : "=r"(r0), "=r"(r1), "=r"(r2), "=r"(r3) : "r"(addr));
}
__device__ __forceinline__ void ldsm4t(uint32_t& r0, uint32_t& r1, uint32_t& r2, uint32_t& r3,
                                       uint32_t addr) {
    asm volatile("ldmatrix.sync.aligned.m8n8.x4.trans.shared.b16 {%0,%1,%2,%3}, [%4];"
                 : "=r"(r0), "=r"(r1), "=r"(r2), "=r"(r3) : "r"(addr));
}
// fp16 m16n8k16, fp32 accumulate
__device__ __forceinline__ void mma16(float* d, const uint32_t* a, uint32_t b0, uint32_t b1) {
    asm volatile("mma.sync.aligned.m16n8k16.row.col.f32.f16.f16.f32 "
                 "{%0,%1,%2,%3}, {%4,%5,%6,%7}, {%8,%9}, {%0,%1,%2,%3};"
                 : "+f"(d[0]), "+f"(d[1]), "+f"(d[2]), "+f"(d[3])
                 : "r"(a[0]), "r"(a[1]), "r"(a[2]), "r"(a[3]), "r"(b0), "r"(b1));
}
__device__ __forceinline__ void cp16(uint32_t dst, const void* src) {
    asm volatile("cp.async.cg.shared.global [%0], [%1], 16;" :: "r"(dst), "l"(src));
}
#define CP_COMMIT() asm volatile("cp.async.commit_group;" ::: "memory")
#define CP_WAIT0()  asm volatile("cp.async.wait_group 0;"  ::: "memory")
#define CP_WAIT1()  asm volatile("cp.async.wait_group 1;"  ::: "memory")

// fp16 hi/lo split of a float4 -> two packed uint2 (4 halves each)
__device__ __forceinline__ void split4(float4 v, uint2& hh, uint2& ll) {
    __half h0 = __float2half_rn(v.x), h1 = __float2half_rn(v.y);
    __half h2 = __float2half_rn(v.z), h3 = __float2half_rn(v.w);
    __half l0 = __float2half_rn(v.x - __half2float(h0));
    __half l1 = __float2half_rn(v.y - __half2float(h1));
    __half l2 = __float2half_rn(v.z - __half2float(h2));
    __half l3 = __float2half_rn(v.w - __half2float(h3));
    __half2 a = __halves2half2(h0, h1), b = __halves2half2(h2, h3);
    __half2 c = __halves2half2(l0, l1), d = __halves2half2(l2, l3);
    hh.x = *(uint32_t*)&a; hh.y = *(uint32_t*)&b;
    ll.x = *(uint32_t*)&c; ll.y = *(uint32_t*)&d;
}

// ===========================================================================
// GEMM 1: S = scale * Q K^T  (2xFP16: (qh+ql)·kh, NT, 128x128, k-chunks of 32)
// ===========================================================================
#define QKC 32
#define QK_NCH (DQK/QKC)           // 16
#define A_PITCH 80                 // 64B data + 16B pad
#define QK_TILE (128*A_PITCH)      // 10240 B
#define QK_STAGE (3*QK_TILE)       // 30720 B (Ah, Al, Bh)

__global__ void __launch_bounds__(256, 2) gemm_qk_f16()
{
    extern __shared__ char smq[];
    const int tid = threadIdx.x, lane = tid & 31, warp = tid >> 5;
    const int wm = warp >> 2, wn = warp & 3;
    const int bz = blockIdx.z, m0 = blockIdx.y*128, n0 = blockIdx.x*128;
    const __half* Ah = g_qh + ((size_t)bz*TSZ + m0)*DQK;
    const __half* Al = g_ql + ((size_t)bz*TSZ + m0)*DQK;
    const __half* Bh = g_kh + ((size_t)bz*TSZ + n0)*DQK;

    float acc[4][4][4];
    #pragma unroll
    for (int i = 0; i < 4; i++)
        #pragma unroll
        for (int j = 0; j < 4; j++)
            #pragma unroll
            for (int k = 0; k < 4; k++) acc[i][j][k] = 0.f;

    const uint32_t sbase = smem_u32(smq);
    const uint32_t aoff = (wm*64 + (lane & 15))*A_PITCH + (lane >> 4)*16;
    const uint32_t boff = (wn*32 + (lane & 7))*A_PITCH + (lane >> 3)*16;

    auto issue = [&](int c, int s) {
        uint32_t dst = sbase + s*QK_STAGE;
        #pragma unroll
        for (int i = 0; i < 2; i++) {
            int idx = tid + 256*i;
            int row = idx >> 2, seg = idx & 3;
            uint32_t d = row*A_PITCH + seg*16;
            size_t sa = (size_t)row*(DQK*2) + (size_t)c*(QKC*2) + seg*16;
            cp16(dst + d,             (const char*)Ah + sa);
            cp16(dst + QK_TILE + d,   (const char*)Al + sa);
            cp16(dst + 2*QK_TILE + d, (const char*)Bh + sa);
        }
        CP_COMMIT();
    };

    issue(0, 0);
    for (int c = 0; c < QK_NCH; c++) {
        CP_WAIT0();
        __syncthreads();
        if (c + 1 < QK_NCH) issue(c+1, (c+1) & 1);
        const uint32_t so = sbase + (c & 1)*QK_STAGE;

        uint32_t bh[4][4];
        #pragma unroll
        for (int in = 0; in < 4; in++)
            ldsm4(bh[in][0], bh[in][1], bh[in][2], bh[in][3],
                  so + 2*QK_TILE + boff + in*(8*A_PITCH));
        #pragma unroll
        for (int ks = 0; ks < 2; ks++) {
            uint32_t ah[4][4], al[4][4];
            #pragma unroll
            for (int im = 0; im < 4; im++) {
                ldsm4(ah[im][0], ah[im][1], ah[im][2], ah[im][3],
                      so + aoff + im*(16*A_PITCH) + ks*32);
                ldsm4(al[im][0], al[im][1], al[im][2], al[im][3],
                      so + QK_TILE + aoff + im*(16*A_PITCH) + ks*32);
            }
            #pragma unroll
            for (int im = 0; im < 4; im++)
                #pragma unroll
                for (int in = 0; in < 4; in++) {
                    mma16(acc[im][in], ah[im], bh[in][2*ks], bh[in][2*ks+1]);
                    mma16(acc[im][in], al[im], bh[in][2*ks], bh[in][2*ks+1]);
                }
        }
    }

    const float scale = 0.0441941738241592f;   // 1/sqrt(512)
    float* Cb = g_s + (size_t)bz*TSZ*TSZ;
    const int mbase = m0 + wm*64, nbase = n0 + wn*32;
    #pragma unroll
    for (int im = 0; im < 4; im++)
        #pragma unroll
        for (int in = 0; in < 4; in++) {
            int rr = mbase + im*16 + (lane >> 2);
            int cc = nbase + in*8 + (lane & 3)*2;
            float2 o0 = make_float2(acc[im][in][0]*scale, acc[im][in][1]*scale);
            float2 o1 = make_float2(acc[im][in][2]*scale, acc[im][in][3]*scale);
            *(float2*)(Cb + (size_t)rr*TSZ + cc)     = o0;
            *(float2*)(Cb + (size_t)(rr+8)*TSZ + cc) = o1;
        }
}

// ===========================================================================
// GEMM 2: O = P V  (single FP16; V via ldmatrix.trans; K-chunk 64; 3-stage)
//   Epilogue writes fp16 AO directly (g_aoh).
// ===========================================================================
#define PVC 64
#define PV_NCH (TSZ/PVC)           // 16
#define PVA_PITCH 144
#define PVB_PITCH 272
#define PVA_TILE (128*PVA_PITCH)   // 18432
#define PVB_TILE (64*PVB_PITCH)    // 17408
#define PV_STAGE (PVA_TILE + PVB_TILE)  // 35840

__global__ void __launch_bounds__(256, 2) gemm_pv_f16()
{
    extern __shared__ char smp[];
    const int tid = threadIdx.x, lane = tid & 31, warp = tid >> 5;
    const int wm = warp >> 2, wn = warp & 3;
    const int bz = blockIdx.z, m0 = blockIdx.y*128, n0 = blockIdx.x*128;
    const __half* A = g_sh + (size_t)bz*TSZ*TSZ + (size_t)m0*TSZ;
    const __half* B = g_vh + (size_t)bz*TSZ*DV;

    float acc[4][4][4];
    #pragma unroll
    for (int i = 0; i < 4; i++)
        #pragma unroll
        for (int j = 0; j < 4; j++)
            #pragma unroll
            for (int k = 0; k < 4; k++) acc[i][j][k] = 0.f;

    const uint32_t sbase = smem_u32(smp);
    const uint32_t aoff = (wm*64 + (lane & 15))*PVA_PITCH + (lane >> 4)*16;
    const uint32_t btoff = PVA_TILE + lane*PVB_PITCH + wn*64;

    auto issue = [&](int c, int s) {
        uint32_t dst = sbase + s*PV_STAGE;
        #pragma unroll
        for (int i = 0; i < 4; i++) {
            int idx = tid + 256*i;
            int ar = idx >> 3, as = idx & 7;
            cp16(dst + ar*PVA_PITCH + as*16,
                 (const char*)A + (size_t)ar*(TSZ*2) + (size_t)c*(PVC*2) + as*16);
            int br = idx >> 4, bs = idx & 15;
            cp16(dst + PVA_TILE + br*PVB_PITCH + bs*16,
                 (const char*)B + ((size_t)(c*PVC + br))*(DV*2) + (size_t)n0*2 + bs*16);
        }
        CP_COMMIT();
    };

    issue(0, 0);
    issue(1, 1);
    for (int c = 0; c < PV_NCH; c++) {
        if (c + 1 < PV_NCH) CP_WAIT1();
        else                CP_WAIT0();
        __syncthreads();
        if (c + 2 < PV_NCH) issue(c+2, (c+2) % 3);
        const uint32_t so = sbase + (c % 3)*PV_STAGE;

        #pragma unroll
        for (int half = 0; half < 2; half++) {
            uint32_t bt[4][4];
            #pragma unroll
            for (int in = 0; in < 4; in++)
                ldsm4t(bt[in][0], bt[in][1], bt[in][2], bt[in][3],
                       so + btoff + half*(32*PVB_PITCH) + in*16);
            #pragma unroll
            for (int ks = 0; ks < 2; ks++) {
                uint32_t a[4][4];
                #pragma unroll
                for (int im = 0; im < 4; im++)
                    ldsm4(a[im][0], a[im][1], a[im][2], a[im][3],
                          so + aoff + im*(16*PVA_PITCH) + (half*2 + ks)*32);
                #pragma unroll
                for (int im = 0; im < 4; im++)
                    #pragma unroll
                    for (int in = 0; in < 4; in++)
                        mma16(acc[im][in], a[im], bt[in][2*ks], bt[in][2*ks+1]);
            }
        }
    }

    const int h = bz >> 2, bb = bz & 3;
    const int cc_ch = h*CHN + blockIdx.x;
    const int mbase = m0 + wm*64, nbase = wn*32;
    __half* Ob = g_aoh + ((size_t)(bb*CSZ + cc_ch)*TSZ)*FSZ;
    #pragma unroll
    for (int im = 0; im < 4; im++)
        #pragma unroll
        for (int in = 0; in < 4; in++) {
            int rr = mbase + im*16 + (lane >> 2);
            int ff = nbase + in*8 + (lane & 3)*2;
            *(__half2*)(Ob + (size_t)rr*FSZ + ff) =
                __floats2half2_rn(acc[im][in][0], acc[im][in][1]);
            *(__half2*)(Ob + (size_t)(rr+8)*FSZ + ff) =
                __floats2half2_rn(acc[im][in][2], acc[im][in][3]);
        }
}

// ===========================================================================
// QKV: per block handles TWO t's. Y[96,128] = Wall[96,64] @ X[64,128] per t.
//   3xFP16 m16n8k16; W converted once, two compute phases.
//   q stored hi/lo; k stored single fp16; v stored fp16.
// ===========================================================================
#define QW_PITCH 144               // 128B (64 halves) + 16 pad
#define QX_PITCH 272               // 256B (128 halves) + 16 pad
#define QX_T (64*QX_PITCH)         // one t's X tile: 17408
#define QKV_WH 0
#define QKV_WL (96*QW_PITCH)                 // 13824
#define QKV_XH (2*96*QW_PITCH)               // 27648
#define QKV_XSZ (2*QX_T)                     // 34816 (2 t's)
#define QKV_XL (QKV_XH + QKV_XSZ)            // 62464
#define QKV_SMEM (QKV_XH + 2*QKV_XSZ)        // 97280

__global__ void __launch_bounds__(256) qkv_f16(
    const float* __restrict__ x,
    const float* __restrict__ Wq, const float* __restrict__ bq,
    const float* __restrict__ aq, const float* __restrict__ gq, const float* __restrict__ beq,
    const float* __restrict__ Wk, const float* __restrict__ bk,
    const float* __restrict__ ak, const float* __restrict__ gk, const float* __restrict__ bek,
    const float* __restrict__ Wv, const float* __restrict__ bv,
    const float* __restrict__ av, const float* __restrict__ gv, const float* __restrict__ bev)
{
    extern __shared__ char sm[];
    __shared__ float rowred[96*2];
    __shared__ float stats[12*2];
    __shared__ float biasS[96], alphS[96];

    const int tid = threadIdx.x, lane = tid & 31, warp = tid >> 5;
    const int wm = warp >> 2, wn = warp & 3;
    const int ly = lane >> 2, lx = lane & 3;
    const int b = blockIdx.x >> 9, t0 = (blockIdx.x & 511)*2;

    if (tid < 96) {
        if (tid < 16)      { biasS[tid] = bq[tid];    alphS[tid] = aq[tid>>2]; }
        else if (tid < 32) { biasS[tid] = bk[tid-16]; alphS[tid] = ak[(tid-16)>>2]; }
        else               { biasS[tid] = bv[tid-32]; alphS[tid] = av[(tid-32)>>4]; }
    }

    // W: 96 rows x 64 floats -> fp16 hi/lo (converted ONCE for both t's)
    #pragma unroll
    for (int j = 0; j < 6; j++) {
        int idx = tid + 256*j;
        int row = idx >> 4, c4 = idx & 15;
        const float* src;
        if (row < 16)      src = Wq + row*CSZ;
        else if (row < 32) src = Wk + (row-16)*CSZ;
        else               src = Wv + (row-32)*CSZ;
        float4 w = *(const float4*)(src + c4*4);
        uint2 hh, ll; split4(w, hh, ll);
        *(uint2*)(sm + QKV_WH + row*QW_PITCH + c4*8) = hh;
        *(uint2*)(sm + QKV_WL + row*QW_PITCH + c4*8) = ll;
    }
    // X: both t's: 2 x 64 c-rows x 128 f (4096 float4, 16/thread)
    #pragma unroll
    for (int j = 0; j < 16; j++) {
        int idx = tid + 256*j;
        int tt = idx >> 11, rem = idx & 2047;
        int c = rem >> 5, f4 = rem & 31;
        float4 v = *(const float4*)(x + (((size_t)(b*CSZ + c))*TSZ + t0 + tt)*FSZ + f4*4);
        uint2 hh, ll; split4(v, hh, ll);
        *(uint2*)(sm + QKV_XH + tt*QX_T + c*QX_PITCH + f4*8) = hh;
        *(uint2*)(sm + QKV_XL + tt*QX_T + c*QX_PITCH + f4*8) = ll;
    }
    __syncthreads();

    const uint32_t sbase = smem_u32(sm);
    const uint32_t awoff = sbase + QKV_WH + (wm*48 + (lane & 15))*QW_PITCH + (lane >> 4)*16;

    for (int tt = 0; tt < 2; tt++) {
        const int t = t0 + tt;
        if (tid < 192) rowred[tid] = 0.f;
        __syncthreads();

        const uint32_t bxoff = sbase + QKV_XH + tt*QX_T + lane*QX_PITCH + wn*64;

        float acc[3][4][4];
        #pragma unroll
        for (int i = 0; i < 3; i++)
            #pragma unroll
            for (int j = 0; j < 4; j++)
                #pragma unroll
                for (int k = 0; k < 4; k++) acc[i][j][k] = 0.f;

        #pragma unroll
        for (int half = 0; half < 2; half++) {
            uint32_t bth[4][4], btl[4][4];
            #pragma unroll
            for (int in = 0; in < 4; in++) {
                ldsm4t(bth[in][0], bth[in][1], bth[in][2], bth[in][3],
                       bxoff + half*(32*QX_PITCH) + in*16);
                ldsm4t(btl[in][0], btl[in][1], btl[in][2], btl[in][3],
                       bxoff + QKV_XSZ + half*(32*QX_PITCH) + in*16);
            }
            #pragma unroll
            for (int ks = 0; ks < 2; ks++) {
                const int kstep = half*2 + ks;
                uint32_t ah[3][4], al[3][4];
                #pragma unroll
                for (int im = 0; im < 3; im++) {
                    ldsm4(ah[im][0], ah[im][1], ah[im][2], ah[im][3],
                          awoff + im*(16*QW_PITCH) + kstep*32);
                    ldsm4(al[im][0], al[im][1], al[im][2], al[im][3],
                          awoff + (QKV_WL - QKV_WH) + im*(16*QW_PITCH) + kstep*32);
                }
                #pragma unroll
                for (int im = 0; im < 3; im++)
                    #pragma unroll
                    for (int in = 0; in < 4; in++) {
                        mma16(acc[im][in], ah[im], bth[in][2*ks], bth[in][2*ks+1]);
                        mma16(acc[im][in], ah[im], btl[in][2*ks], btl[in][2*ks+1]);
                        mma16(acc[im][in], al[im], bth[in][2*ks], bth[in][2*ks+1]);
                    }
            }
        }

        // bias + PReLU + per-row partial sums
        float rs[3][2], rq[3][2];
        #pragma unroll
        for (int im = 0; im < 3; im++) { rs[im][0]=rs[im][1]=0.f; rq[im][0]=rq[im][1]=0.f; }
        #pragma unroll
        for (int im = 0; im < 3; im++)
            #pragma unroll
            for (int hh = 0; hh < 2; hh++) {
                int r = wm*48 + im*16 + ly + hh*8;
                float bi = biasS[r], alp = alphS[r];
                #pragma unroll
                for (int in = 0; in < 4; in++)
                    #pragma unroll
                    for (int e = 0; e < 2; e++) {
                        float y = acc[im][in][hh*2+e] + bi;
                        y = y > 0.f ? y : alp*y;
                        acc[im][in][hh*2+e] = y;
                        rs[im][hh] += y; rq[im][hh] += y*y;
                    }
            }
        #pragma unroll
        for (int im = 0; im < 3; im++)
            #pragma unroll
            for (int hh = 0; hh < 2; hh++) {
                float s = rs[im][hh], q = rq[im][hh];
                s += __shfl_xor_sync(0xffffffffu, s, 1); q += __shfl_xor_sync(0xffffffffu, q, 1);
                s += __shfl_xor_sync(0xffffffffu, s, 2); q += __shfl_xor_sync(0xffffffffu, q, 2);
                if (lx == 0) {
                    int r = wm*48 + im*16 + ly + hh*8;
                    atomicAdd(&rowred[2*r], s); atomicAdd(&rowred[2*r+1], q);
                }
            }
        __syncthreads();
        if (tid < 12) {
            int st, cnt;
            if (tid < 8) { st = tid*4; cnt = 4; } else { st = 32 + (tid-8)*16; cnt = 16; }
            float s = 0.f, q = 0.f;
            for (int r = st; r < st+cnt; r++) { s += rowred[2*r]; q += rowred[2*r+1]; }
            float inv = 1.f/(cnt*FSZ);
            float mean = s*inv, var = q*inv - mean*mean;
            stats[2*tid] = mean; stats[2*tid+1] = rsqrtf(var + 1e-5f);
        }
        __syncthreads();

        // normalize + store (q fp16 hi/lo; k fp16; v fp16)
        #pragma unroll
        for (int im = 0; im < 3; im++)
            #pragma unroll
            for (int hh = 0; hh < 2; hh++) {
                int r = wm*48 + im*16 + ly + hh*8;
                int grp = (r < 32) ? (r >> 2) : ((r >> 4) + 6);
                float mean = stats[2*grp], rstd = stats[2*grp+1];
                if (r < 16) {
                    int jrow = r;
                    size_t off = (((size_t)((jrow>>2)*BSZ + b)*TSZ + t)*DQK) + (jrow&3)*FSZ;
                    __half* dh = g_qh + off;
                    __half* dl = g_ql + off;
                    #pragma unroll
                    for (int in = 0; in < 4; in++) {
                        int c = wn*32 + in*8 + lx*2;
                        float y0 = (acc[im][in][hh*2+0]-mean)*rstd*gq[jrow*FSZ+c]   + beq[jrow*FSZ+c];
                        float y1 = (acc[im][in][hh*2+1]-mean)*rstd*gq[jrow*FSZ+c+1] + beq[jrow*FSZ+c+1];
                        __half h0 = __float2half_rn(y0), h1 = __float2half_rn(y1);
                        __half l0 = __float2half_rn(y0 - __half2float(h0));
                        __half l1 = __float2half_rn(y1 - __half2float(h1));
                        *(__half2*)(dh + c) = __halves2half2(h0, h1);
                        *(__half2*)(dl + c) = __halves2half2(l0, l1);
                    }
                } else if (r < 32) {
                    int jrow = r - 16;
                    size_t off = (((size_t)((jrow>>2)*BSZ + b)*TSZ + t)*DQK) + (jrow&3)*FSZ;
                    __half* dst = g_kh + off;
                    #pragma unroll
                    for (int in = 0; in < 4; in++) {
                        int c = wn*32 + in*8 + lx*2;
                        float y0 = (acc[im][in][hh*2+0]-mean)*rstd*gk[jrow*FSZ+c]   + bek[jrow*FSZ+c];
                        float y1 = (acc[im][in][hh*2+1]-mean)*rstd*gk[jrow*FSZ+c+1] + bek[jrow*FSZ+c+1];
                        *(__half2*)(dst + c) = __floats2half2_rn(y0, y1);
                    }
                } else {
                    int jrow = r - 32;
                    __half* dst = g_vh + (((size_t)((jrow>>4)*BSZ + b)*TSZ + t)*DV) + (jrow&15)*FSZ;
                    #pragma unroll
                    for (int in = 0; in < 4; in++) {
                        int c = wn*32 + in*8 + lx*2;
                        float y0 = (acc[im][in][hh*2+0]-mean)*rstd*gv[jrow*FSZ+c]   + bev[jrow*FSZ+c];
                        float y1 = (acc[im][in][hh*2+1]-mean)*rstd*gv[jrow*FSZ+c+1] + bev[jrow*FSZ+c+1];
                        *(__half2*)(dst + c) = __floats2half2_rn(y0, y1);
                    }
                }
            }
        __syncthreads();
    }
}

// ===========================================================================
// PROJ: per block TWO t's. Y[64,128] = Wp[64,64] @ AO[64,128] per t.
//   AO is fp16 (g_aoh) -> X loaded raw via cp.async; 2-term split (W only).
// ===========================================================================
#define PJX_PITCH 272
#define PJX_T (64*PJX_PITCH)                 // 17408
#define PJ_WH 0
#define PJ_WL (64*QW_PITCH)                  // 9216
#define PJ_X  (2*64*QW_PITCH)                // 18432
#define PJ_SMEM (PJ_X + 2*PJX_T)             // 53248

__global__ void __launch_bounds__(256) proj_f16(
    const float* __restrict__ x, const float* __restrict__ Wp,
    const float* __restrict__ bp, const float* __restrict__ ap,
    const float* __restrict__ gp, const float* __restrict__ bep,
    float* __restrict__ out)
{
    extern __shared__ char sm[];
    __shared__ float red[2];
    __shared__ float statv[2];

    const int tid = threadIdx.x, lane = tid & 31, warp = tid >> 5;
    const int wm = warp >> 2, wn = warp & 3;
    const int ly = lane >> 2, lx = lane & 3;
    const int b = blockIdx.x >> 9, t0 = (blockIdx.x & 511)*2;

    const uint32_t sbase = smem_u32(sm);

    // X = AO (fp16): raw cp.async, both t's.
    #pragma unroll
    for (int j = 0; j < 8; j++) {
        int idx = tid + 256*j;
        int tt = idx >> 10, rem = idx & 1023;
        int c = rem >> 4, seg = rem & 15;
        cp16(sbase + PJ_X + tt*PJX_T + c*PJX_PITCH + seg*16,
             (const char*)(g_aoh + (((size_t)(b*CSZ + c))*TSZ + t0 + tt)*FSZ) + seg*16);
    }
    CP_COMMIT();

    // W: 64 rows x 64 floats (hi/lo)
    #pragma unroll
    for (int j = 0; j < 4; j++) {
        int idx = tid + 256*j;
        int row = idx >> 4, c4 = idx & 15;
        float4 w = *(const float4*)(Wp + row*CSZ + c4*4);
        uint2 hh, ll; split4(w, hh, ll);
        *(uint2*)(sm + PJ_WH + row*QW_PITCH + c4*8) = hh;
        *(uint2*)(sm + PJ_WL + row*QW_PITCH + c4*8) = ll;
    }
    CP_WAIT0();
    __syncthreads();

    const uint32_t awoff = sbase + PJ_WH + (wm*32 + (lane & 15))*QW_PITCH + (lane >> 4)*16;

    for (int tt = 0; tt < 2; tt++) {
        const int t = t0 + tt;
        if (tid < 2) red[tid] = 0.f;
        __syncthreads();

        const uint32_t bxoff = sbase + PJ_X + tt*PJX_T + lane*PJX_PITCH + wn*64;

        float acc[2][4][4];
        #pragma unroll
        for (int i = 0; i < 2; i++)
            #pragma unroll
            for (int j = 0; j < 4; j++)
                #pragma unroll
                for (int k = 0; k < 4; k++) acc[i][j][k] = 0.f;

        #pragma unroll
        for (int half = 0; half < 2; half++) {
            uint32_t bt[4][4];
            #pragma unroll
            for (int in = 0; in < 4; in++)
                ldsm4t(bt[in][0], bt[in][1], bt[in][2], bt[in][3],
                       bxoff + half*(32*PJX_PITCH) + in*16);
            #pragma unroll
            for (int ks = 0; ks < 2; ks++) {
                const int kstep = half*2 + ks;
                uint32_t ah[2][4], al[2][4];
                #pragma unroll
                for (int im = 0; im < 2; im++) {
                    ldsm4(ah[im][0], ah[im][1], ah[im][2], ah[im][3],
                          awoff + im*(16*QW_PITCH) + kstep*32);
                    ldsm4(al[im][0], al[im][1], al[im][2], al[im][3],
                          awoff + (PJ_WL - PJ_WH) + im*(16*QW_PITCH) + kstep*32);
                }
                #pragma unroll
                for (int im = 0; im < 2; im++)
                    #pragma unroll
                    for (int in = 0; in < 4; in++) {
                        mma16(acc[im][in], ah[im], bt[in][2*ks], bt[in][2*ks+1]);
                        mma16(acc[im][in], al[im], bt[in][2*ks], bt[in][2*ks+1]);
                    }
            }
        }

        const float alp = ap[0];
        float s1 = 0.f, s2 = 0.f;
        #pragma unroll
        for (int im = 0; im < 2; im++)
            #pragma unroll
            for (int hh = 0; hh < 2; hh++) {
                int r = wm*32 + im*16 + ly + hh*8;
                float bi = bp[r];
                #pragma unroll
                for (int in = 0; in < 4; in++)
                    #pragma unroll
                    for (int e = 0; e < 2; e++) {
                        float y = acc[im][in][hh*2+e] + bi;
                        y = y > 0.f ? y : alp*y;
                        acc[im][in][hh*2+e] = y;
                        s1 += y; s2 += y*y;
                    }
            }
        #pragma unroll
        for (int off = 16; off; off >>= 1) {
            s1 += __shfl_xor_sync(0xffffffffu, s1, off);
            s2 += __shfl_xor_sync(0xffffffffu, s2, off);
        }
        if (lane == 0) { atomicAdd(&red[0], s1); atomicAdd(&red[1], s2); }
        __syncthreads();
        if (tid == 0) {
            const float invn = 1.f/(CSZ*FSZ);
            float mean = red[0]*invn, var = red[1]*invn - mean*mean;
            statv[0] = mean; statv[1] = rsqrtf(var + 1e-5f);
        }
        __syncthreads();
        const float mean = statv[0], rstd = statv[1];

        #pragma unroll
        for (int im = 0; im < 2; im++)
            #pragma unroll
            for (int hh = 0; hh < 2; hh++) {
                int r = wm*32 + im*16 + ly + hh*8;
                size_t rowoff = (((size_t)(b*CSZ + r))*TSZ + t)*FSZ;
                #pragma unroll
                for (int in = 0; in < 4; in++) {
                    int c = wn*32 + in*8 + lx*2;
                    float2 xr = *(const float2*)(x + rowoff + c);
                    float y0 = (acc[im][in][hh*2+0]-mean)*rstd*gp[r*FSZ+c]   + bep[r*FSZ+c]   + xr.x;
                    float y1 = (acc[im][in][hh*2+1]-mean)*rstd*gp[r*FSZ+c+1] + bep[r*FSZ+c+1] + xr.y;
                    *(float2*)(out + rowoff + c) = make_float2(y0, y1);
                }
            }
        __syncthreads();
    }
}

// ===========================================================================
// Softmax: fp32 logits in, fp16 P out
// ===========================================================================
__global__ void __launch_bounds__(256) softmax_kernel()
{
    const size_t row = blockIdx.x;
    const float4* p4 = reinterpret_cast<const float4*>(g_s) + row*256;
    const int tid = threadIdx.x, lane = tid & 31, warp = tid >> 5;
    __shared__ float sred[8];

    float4 v = p4[tid];
    float m = fmaxf(fmaxf(v.x, v.y), fmaxf(v.z, v.w));
    #pragma unroll
    for (int off = 16; off; off >>= 1) m = fmaxf(m, __shfl_xor_sync(0xffffffffu, m, off));
    if (lane == 0) sred[warp] = m;
    __syncthreads();
    float mm = sred[0];
    #pragma unroll
    for (int i = 1; i < 8; i++) mm = fmaxf(mm, sred[i]);
    __syncthreads();

    v.x = __expf(v.x - mm); v.y = __expf(v.y - mm);
    v.z = __expf(v.z - mm); v.w = __expf(v.w - mm);
    float s = v.x + v.y + v.z + v.w;
    #pragma unroll
    for (int off = 16; off; off >>= 1) s += __shfl_xor_sync(0xffffffffu, s, off);
    if (lane == 0) sred[warp] = s;
    __syncthreads();
    float ss = sred[0];
    #pragma unroll
    for (int i = 1; i < 8; i++) ss += sred[i];
    float inv = 1.0f/ss;

    __half2 h0 = __floats2half2_rn(v.x*inv, v.y*inv);
    __half2 h1 = __floats2half2_rn(v.z*inv, v.w*inv);
    __half2* o2 = reinterpret_cast<__half2*>(g_sh + row*TSZ);
    o2[tid*2]   = h0;
    o2[tid*2+1] = h1;
}

// ===========================================================================
extern "C" void kernel_launch(void* const* d_in, const int* in_sizes, int n_in,
                              void* d_out, int out_size)
{
    const float* x   = (const float*)d_in[0];
    const float* Wq  = (const float*)d_in[1];
    const float* bq  = (const float*)d_in[2];
    const float* aq  = (const float*)d_in[3];
    const float* gq  = (const float*)d_in[4];
    const float* beq = (const float*)d_in[5];
    const float* Wk  = (const float*)d_in[6];
    const float* bk  = (const float*)d_in[7];
    const float* ak  = (const float*)d_in[8];
    const float* gk  = (const float*)d_in[9];
    const float* bek = (const float*)d_in[10];
    const float* Wv  = (const float*)d_in[11];
    const float* bv  = (const float*)d_in[12];
    const float* av  = (const float*)d_in[13];
    const float* gv  = (const float*)d_in[14];
    const float* bev = (const float*)d_in[15];
    const float* Wp  = (const float*)d_in[16];
    const float* bp  = (const float*)d_in[17];
    const float* ap  = (const float*)d_in[18];
    const float* gp  = (const float*)d_in[19];
    const float* bep = (const float*)d_in[20];
    float* out = (float*)d_out;

    const int SMEM_QK = 2*QK_STAGE;    // 61440
    const int SMEM_PV = 3*PV_STAGE;    // 107520
    cudaFuncSetAttribute(qkv_f16,     cudaFuncAttributeMaxDynamicSharedMemorySize, QKV_SMEM);
    cudaFuncSetAttribute(proj_f16,    cudaFuncAttributeMaxDynamicSharedMemorySize, PJ_SMEM);
    cudaFuncSetAttribute(gemm_qk_f16, cudaFuncAttributeMaxDynamicSharedMemorySize, SMEM_QK);
    cudaFuncSetAttribute(gemm_pv_f16, cudaFuncAttributeMaxDynamicSharedMemorySize, SMEM_PV);

    qkv_f16<<<BSZ*TSZ/2, 256, QKV_SMEM>>>(x, Wq, bq, aq, gq, beq,
                                          Wk, bk, ak, gk, bek,
                                          Wv, bv, av, gv, bev);
    gemm_qk_f16<<<dim3(8, 8, NB), 256, SMEM_QK>>>();
    softmax_kernel<<<NB*TSZ, 256>>>();
    gemm_pv_f16<<<dim3(16, 8, NB), 256, SMEM_PV>>>();
    proj_f16<<<BSZ*TSZ/2, 256, PJ_SMEM>>>(x, Wp, bp, ap, gp, bep, out);
}

// round 15
// speedup vs baseline: 1.2303x; 1.0846x over previous
#include <cuda_runtime.h>
#include <cuda_fp16.h>
#include <cstdint>

// Problem constants
#define BSZ 4
#define CSZ 64
#define TSZ 1024
#define FSZ 128
#define HN  4
#define HIDN 4
#define CHN 16
#define NB  (HN*BSZ)      // 16 attention batches
#define DQK (HIDN*FSZ)    // 512
#define DV  (CHN*FSZ)     // 2048

// Scratch (device globals: allocation-free rule)
__device__ __half g_qh[(size_t)NB*TSZ*DQK];          // q fp16 [n][t][d]
__device__ __half g_kh[(size_t)NB*TSZ*DQK];          // k fp16 [n][t][d]
__device__ __half g_vh[(size_t)NB*TSZ*DV];           // v fp16 [n][t][d]
__device__ float  g_s [(size_t)NB*TSZ*TSZ];          // logits fp32
__device__ __half g_sh[(size_t)NB*TSZ*TSZ];          // P fp16 [n][t][t']
__device__ __half g_aoh[(size_t)BSZ*CSZ*TSZ*FSZ];    // attention out, fp16

// ===========================================================================
// helpers
// ===========================================================================
__device__ __forceinline__ uint32_t smem_u32(const void* p) {
    uint32_t a;
    asm("{ .reg .u64 t; cvta.to.shared.u64 t, %1; cvt.u32.u64 %0, t; }" : "=r"(a) : "l"(p));
    return a;
}
__device__ __forceinline__ void ldsm4(uint32_t& r0, uint32_t& r1, uint32_t& r2, uint32_t& r3,
                                      uint32_t addr) {
    asm volatile("ldmatrix.sync.aligned.m8n8.x4.shared.b16 {%0,%1,%2,%3}, [%4];"
                 : "=r"(r0), "=r"(r1), "=r"(r2), "=r"(r3) : "r"(addr));
}
__device__ __forceinline__ void ldsm4t(uint32_t& r0, uint32_t& r1, uint32_t& r2, uint32_t& r3,
                                       uint32_t addr) {
    asm volatile("ldmatrix.sync.aligned.m8n8.x4.trans.shared.b16 {%0,%1,%2,%3}, [%4];"
                 : "=r"(r0), "=r"(r1), "=r"(r2), "=r"(r3) : "r"(addr));
}
// fp16 m16n8k16, fp32 accumulate
__device__ __forceinline__ void mma16(float* d, const uint32_t* a, uint32_t b0, uint32_t b1) {
    asm volatile("mma.sync.aligned.m16n8k16.row.col.f32.f16.f16.f32 "
                 "{%0,%1,%2,%3}, {%4,%5,%6,%7}, {%8,%9}, {%0,%1,%2,%3};"
                 : "+f"(d[0]), "+f"(d[1]), "+f"(d[2]), "+f"(d[3])
                 : "r"(a[0]), "r"(a[1]), "r"(a[2]), "r"(a[3]), "r"(b0), "r"(b1));
}
__device__ __forceinline__ void cp16(uint32_t dst, const void* src) {
    asm volatile("cp.async.cg.shared.global [%0], [%1], 16;" :: "r"(dst), "l"(src));
}
#define CP_COMMIT() asm volatile("cp.async.commit_group;" ::: "memory")
#define CP_WAIT0()  asm volatile("cp.async.wait_group 0;"  ::: "memory")
#define CP_WAIT1()  asm volatile("cp.async.wait_group 1;"  ::: "memory")

// fp16 hi/lo split of a float4 -> two packed uint2 (4 halves each)
__device__ __forceinline__ void split4(float4 v, uint2& hh, uint2& ll) {
    __half h0 = __float2half_rn(v.x), h1 = __float2half_rn(v.y);
    __half h2 = __float2half_rn(v.z), h3 = __float2half_rn(v.w);
    __half l0 = __float2half_rn(v.x - __half2float(h0));
    __half l1 = __float2half_rn(v.y - __half2float(h1));
    __half l2 = __float2half_rn(v.z - __half2float(h2));
    __half l3 = __float2half_rn(v.w - __half2float(h3));
    __half2 a = __halves2half2(h0, h1), b = __halves2half2(h2, h3);
    __half2 c = __halves2half2(l0, l1), d = __halves2half2(l2, l3);
    hh.x = *(uint32_t*)&a; hh.y = *(uint32_t*)&b;
    ll.x = *(uint32_t*)&c; ll.y = *(uint32_t*)&d;
}

// ===========================================================================
// GEMM 1: S = scale * Q K^T  (single FP16, NT, 128x128, k-chunks of 64, 2-stage)
// ===========================================================================
#define QKC 64
#define QK_NCH (DQK/QKC)           // 8
#define QKP 144                    // 128B data + 16B pad
#define QK_TILE (128*QKP)          // 18432 B
#define QK_STAGE (2*QK_TILE)       // 36864 B (A, B)

__global__ void __launch_bounds__(256, 2) gemm_qk_f16()
{
    extern __shared__ char smq[];
    const int tid = threadIdx.x, lane = tid & 31, warp = tid >> 5;
    const int wm = warp >> 2, wn = warp & 3;
    const int bz = blockIdx.z, m0 = blockIdx.y*128, n0 = blockIdx.x*128;
    const __half* A = g_qh + ((size_t)bz*TSZ + m0)*DQK;
    const __half* B = g_kh + ((size_t)bz*TSZ + n0)*DQK;

    float acc[4][4][4];
    #pragma unroll
    for (int i = 0; i < 4; i++)
        #pragma unroll
        for (int j = 0; j < 4; j++)
            #pragma unroll
            for (int k = 0; k < 4; k++) acc[i][j][k] = 0.f;

    const uint32_t sbase = smem_u32(smq);
    const uint32_t aoff = (wm*64 + (lane & 15))*QKP + (lane >> 4)*16;
    const uint32_t boff = QK_TILE + (wn*32 + (lane & 7))*QKP + (lane >> 3)*16;

    auto issue = [&](int c, int s) {
        uint32_t dst = sbase + s*QK_STAGE;
        #pragma unroll
        for (int i = 0; i < 4; i++) {
            int idx = tid + 256*i;                 // 0..1023
            int row = idx >> 3, seg = idx & 7;
            uint32_t d = row*QKP + seg*16;
            size_t sa = (size_t)row*(DQK*2) + (size_t)c*(QKC*2) + seg*16;
            cp16(dst + d,           (const char*)A + sa);
            cp16(dst + QK_TILE + d, (const char*)B + sa);
        }
        CP_COMMIT();
    };

    issue(0, 0);
    for (int c = 0; c < QK_NCH; c++) {
        CP_WAIT0();
        __syncthreads();
        if (c + 1 < QK_NCH) issue(c+1, (c+1) & 1);
        const uint32_t so = sbase + (c & 1)*QK_STAGE;

        #pragma unroll
        for (int half = 0; half < 2; half++) {
            uint32_t bh[4][4];
            #pragma unroll
            for (int in = 0; in < 4; in++)
                ldsm4(bh[in][0], bh[in][1], bh[in][2], bh[in][3],
                      so + boff + half*64 + in*(8*QKP));
            #pragma unroll
            for (int ks = 0; ks < 2; ks++) {
                uint32_t a[4][4];
                #pragma unroll
                for (int im = 0; im < 4; im++)
                    ldsm4(a[im][0], a[im][1], a[im][2], a[im][3],
                          so + aoff + im*(16*QKP) + (half*2 + ks)*32);
                #pragma unroll
                for (int im = 0; im < 4; im++)
                    #pragma unroll
                    for (int in = 0; in < 4; in++)
                        mma16(acc[im][in], a[im], bh[in][2*ks], bh[in][2*ks+1]);
            }
        }
    }

    const float scale = 0.0441941738241592f;   // 1/sqrt(512)
    float* Cb = g_s + (size_t)bz*TSZ*TSZ;
    const int mbase = m0 + wm*64, nbase = n0 + wn*32;
    #pragma unroll
    for (int im = 0; im < 4; im++)
        #pragma unroll
        for (int in = 0; in < 4; in++) {
            int rr = mbase + im*16 + (lane >> 2);
            int cc = nbase + in*8 + (lane & 3)*2;
            float2 o0 = make_float2(acc[im][in][0]*scale, acc[im][in][1]*scale);
            float2 o1 = make_float2(acc[im][in][2]*scale, acc[im][in][3]*scale);
            *(float2*)(Cb + (size_t)rr*TSZ + cc)     = o0;
            *(float2*)(Cb + (size_t)(rr+8)*TSZ + cc) = o1;
        }
}

// ===========================================================================
// GEMM 2: O = P V  (single FP16; V via ldmatrix.trans; K-chunk 64; 3-stage)
//   Epilogue writes fp16 AO directly (g_aoh).
// ===========================================================================
#define PVC 64
#define PV_NCH (TSZ/PVC)           // 16
#define PVA_PITCH 144
#define PVB_PITCH 272
#define PVA_TILE (128*PVA_PITCH)   // 18432
#define PVB_TILE (64*PVB_PITCH)    // 17408
#define PV_STAGE (PVA_TILE + PVB_TILE)  // 35840

__global__ void __launch_bounds__(256, 2) gemm_pv_f16()
{
    extern __shared__ char smp[];
    const int tid = threadIdx.x, lane = tid & 31, warp = tid >> 5;
    const int wm = warp >> 2, wn = warp & 3;
    const int bz = blockIdx.z, m0 = blockIdx.y*128, n0 = blockIdx.x*128;
    const __half* A = g_sh + (size_t)bz*TSZ*TSZ + (size_t)m0*TSZ;
    const __half* B = g_vh + (size_t)bz*TSZ*DV;

    float acc[4][4][4];
    #pragma unroll
    for (int i = 0; i < 4; i++)
        #pragma unroll
        for (int j = 0; j < 4; j++)
            #pragma unroll
            for (int k = 0; k < 4; k++) acc[i][j][k] = 0.f;

    const uint32_t sbase = smem_u32(smp);
    const uint32_t aoff = (wm*64 + (lane & 15))*PVA_PITCH + (lane >> 4)*16;
    const uint32_t btoff = PVA_TILE + lane*PVB_PITCH + wn*64;

    auto issue = [&](int c, int s) {
        uint32_t dst = sbase + s*PV_STAGE;
        #pragma unroll
        for (int i = 0; i < 4; i++) {
            int idx = tid + 256*i;
            int ar = idx >> 3, as = idx & 7;
            cp16(dst + ar*PVA_PITCH + as*16,
                 (const char*)A + (size_t)ar*(TSZ*2) + (size_t)c*(PVC*2) + as*16);
            int br = idx >> 4, bs = idx & 15;
            cp16(dst + PVA_TILE + br*PVB_PITCH + bs*16,
                 (const char*)B + ((size_t)(c*PVC + br))*(DV*2) + (size_t)n0*2 + bs*16);
        }
        CP_COMMIT();
    };

    issue(0, 0);
    issue(1, 1);
    for (int c = 0; c < PV_NCH; c++) {
        if (c + 1 < PV_NCH) CP_WAIT1();
        else                CP_WAIT0();
        __syncthreads();
        if (c + 2 < PV_NCH) issue(c+2, (c+2) % 3);
        const uint32_t so = sbase + (c % 3)*PV_STAGE;

        #pragma unroll
        for (int half = 0; half < 2; half++) {
            uint32_t bt[4][4];
            #pragma unroll
            for (int in = 0; in < 4; in++)
                ldsm4t(bt[in][0], bt[in][1], bt[in][2], bt[in][3],
                       so + btoff + half*(32*PVB_PITCH) + in*16);
            #pragma unroll
            for (int ks = 0; ks < 2; ks++) {
                uint32_t a[4][4];
                #pragma unroll
                for (int im = 0; im < 4; im++)
                    ldsm4(a[im][0], a[im][1], a[im][2], a[im][3],
                          so + aoff + im*(16*PVA_PITCH) + (half*2 + ks)*32);
                #pragma unroll
                for (int im = 0; im < 4; im++)
                    #pragma unroll
                    for (int in = 0; in < 4; in++)
                        mma16(acc[im][in], a[im], bt[in][2*ks], bt[in][2*ks+1]);
            }
        }
    }

    const int h = bz >> 2, bb = bz & 3;
    const int cc_ch = h*CHN + blockIdx.x;
    const int mbase = m0 + wm*64, nbase = wn*32;
    __half* Ob = g_aoh + ((size_t)(bb*CSZ + cc_ch)*TSZ)*FSZ;
    #pragma unroll
    for (int im = 0; im < 4; im++)
        #pragma unroll
        for (int in = 0; in < 4; in++) {
            int rr = mbase + im*16 + (lane >> 2);
            int ff = nbase + in*8 + (lane & 3)*2;
            *(__half2*)(Ob + (size_t)rr*FSZ + ff) =
                __floats2half2_rn(acc[im][in][0], acc[im][in][1]);
            *(__half2*)(Ob + (size_t)(rr+8)*FSZ + ff) =
                __floats2half2_rn(acc[im][in][2], acc[im][in][3]);
        }
}

// ===========================================================================
// QKV: per block handles TWO t's. Y[96,128] = Wall[96,64] @ X[64,128] per t.
//   3xFP16 m16n8k16; W converted once, two compute phases.
//   q, k, v all stored single fp16.
// ===========================================================================
#define QW_PITCH 144               // 128B (64 halves) + 16 pad
#define QX_PITCH 272               // 256B (128 halves) + 16 pad
#define QX_T (64*QX_PITCH)         // one t's X tile: 17408
#define QKV_WH 0
#define QKV_WL (96*QW_PITCH)                 // 13824
#define QKV_XH (2*96*QW_PITCH)               // 27648
#define QKV_XSZ (2*QX_T)                     // 34816 (2 t's)
#define QKV_XL (QKV_XH + QKV_XSZ)            // 62464
#define QKV_SMEM (QKV_XH + 2*QKV_XSZ)        // 97280

__global__ void __launch_bounds__(256) qkv_f16(
    const float* __restrict__ x,
    const float* __restrict__ Wq, const float* __restrict__ bq,
    const float* __restrict__ aq, const float* __restrict__ gq, const float* __restrict__ beq,
    const float* __restrict__ Wk, const float* __restrict__ bk,
    const float* __restrict__ ak, const float* __restrict__ gk, const float* __restrict__ bek,
    const float* __restrict__ Wv, const float* __restrict__ bv,
    const float* __restrict__ av, const float* __restrict__ gv, const float* __restrict__ bev)
{
    extern __shared__ char sm[];
    __shared__ float rowred[96*2];
    __shared__ float stats[12*2];
    __shared__ float biasS[96], alphS[96];

    const int tid = threadIdx.x, lane = tid & 31, warp = tid >> 5;
    const int wm = warp >> 2, wn = warp & 3;
    const int ly = lane >> 2, lx = lane & 3;
    const int b = blockIdx.x >> 9, t0 = (blockIdx.x & 511)*2;

    if (tid < 96) {
        if (tid < 16)      { biasS[tid] = bq[tid];    alphS[tid] = aq[tid>>2]; }
        else if (tid < 32) { biasS[tid] = bk[tid-16]; alphS[tid] = ak[(tid-16)>>2]; }
        else               { biasS[tid] = bv[tid-32]; alphS[tid] = av[(tid-32)>>4]; }
    }

    // W: 96 rows x 64 floats -> fp16 hi/lo (converted ONCE for both t's)
    #pragma unroll
    for (int j = 0; j < 6; j++) {
        int idx = tid + 256*j;
        int row = idx >> 4, c4 = idx & 15;
        const float* src;
        if (row < 16)      src = Wq + row*CSZ;
        else if (row < 32) src = Wk + (row-16)*CSZ;
        else               src = Wv + (row-32)*CSZ;
        float4 w = *(const float4*)(src + c4*4);
        uint2 hh, ll; split4(w, hh, ll);
        *(uint2*)(sm + QKV_WH + row*QW_PITCH + c4*8) = hh;
        *(uint2*)(sm + QKV_WL + row*QW_PITCH + c4*8) = ll;
    }
    // X: both t's: 2 x 64 c-rows x 128 f (4096 float4, 16/thread)
    #pragma unroll
    for (int j = 0; j < 16; j++) {
        int idx = tid + 256*j;
        int tt = idx >> 11, rem = idx & 2047;
        int c = rem >> 5, f4 = rem & 31;
        float4 v = *(const float4*)(x + (((size_t)(b*CSZ + c))*TSZ + t0 + tt)*FSZ + f4*4);
        uint2 hh, ll; split4(v, hh, ll);
        *(uint2*)(sm + QKV_XH + tt*QX_T + c*QX_PITCH + f4*8) = hh;
        *(uint2*)(sm + QKV_XL + tt*QX_T + c*QX_PITCH + f4*8) = ll;
    }
    __syncthreads();

    const uint32_t sbase = smem_u32(sm);
    const uint32_t awoff = sbase + QKV_WH + (wm*48 + (lane & 15))*QW_PITCH + (lane >> 4)*16;

    for (int tt = 0; tt < 2; tt++) {
        const int t = t0 + tt;
        if (tid < 192) rowred[tid] = 0.f;
        __syncthreads();

        const uint32_t bxoff = sbase + QKV_XH + tt*QX_T + lane*QX_PITCH + wn*64;

        float acc[3][4][4];
        #pragma unroll
        for (int i = 0; i < 3; i++)
            #pragma unroll
            for (int j = 0; j < 4; j++)
                #pragma unroll
                for (int k = 0; k < 4; k++) acc[i][j][k] = 0.f;

        #pragma unroll
        for (int half = 0; half < 2; half++) {
            uint32_t bth[4][4], btl[4][4];
            #pragma unroll
            for (int in = 0; in < 4; in++) {
                ldsm4t(bth[in][0], bth[in][1], bth[in][2], bth[in][3],
                       bxoff + half*(32*QX_PITCH) + in*16);
                ldsm4t(btl[in][0], btl[in][1], btl[in][2], btl[in][3],
                       bxoff + QKV_XSZ + half*(32*QX_PITCH) + in*16);
            }
            #pragma unroll
            for (int ks = 0; ks < 2; ks++) {
                const int kstep = half*2 + ks;
                uint32_t ah[3][4], al[3][4];
                #pragma unroll
                for (int im = 0; im < 3; im++) {
                    ldsm4(ah[im][0], ah[im][1], ah[im][2], ah[im][3],
                          awoff + im*(16*QW_PITCH) + kstep*32);
                    ldsm4(al[im][0], al[im][1], al[im][2], al[im][3],
                          awoff + (QKV_WL - QKV_WH) + im*(16*QW_PITCH) + kstep*32);
                }
                #pragma unroll
                for (int im = 0; im < 3; im++)
                    #pragma unroll
                    for (int in = 0; in < 4; in++) {
                        mma16(acc[im][in], ah[im], bth[in][2*ks], bth[in][2*ks+1]);
                        mma16(acc[im][in], ah[im], btl[in][2*ks], btl[in][2*ks+1]);
                        mma16(acc[im][in], al[im], bth[in][2*ks], bth[in][2*ks+1]);
                    }
            }
        }

        // bias + PReLU + per-row partial sums
        float rs[3][2], rq[3][2];
        #pragma unroll
        for (int im = 0; im < 3; im++) { rs[im][0]=rs[im][1]=0.f; rq[im][0]=rq[im][1]=0.f; }
        #pragma unroll
        for (int im = 0; im < 3; im++)
            #pragma unroll
            for (int hh = 0; hh < 2; hh++) {
                int r = wm*48 + im*16 + ly + hh*8;
                float bi = biasS[r], alp = alphS[r];
                #pragma unroll
                for (int in = 0; in < 4; in++)
                    #pragma unroll
                    for (int e = 0; e < 2; e++) {
                        float y = acc[im][in][hh*2+e] + bi;
                        y = y > 0.f ? y : alp*y;
                        acc[im][in][hh*2+e] = y;
                        rs[im][hh] += y; rq[im][hh] += y*y;
                    }
            }
        #pragma unroll
        for (int im = 0; im < 3; im++)
            #pragma unroll
            for (int hh = 0; hh < 2; hh++) {
                float s = rs[im][hh], q = rq[im][hh];
                s += __shfl_xor_sync(0xffffffffu, s, 1); q += __shfl_xor_sync(0xffffffffu, q, 1);
                s += __shfl_xor_sync(0xffffffffu, s, 2); q += __shfl_xor_sync(0xffffffffu, q, 2);
                if (lx == 0) {
                    int r = wm*48 + im*16 + ly + hh*8;
                    atomicAdd(&rowred[2*r], s); atomicAdd(&rowred[2*r+1], q);
                }
            }
        __syncthreads();
        if (tid < 12) {
            int st, cnt;
            if (tid < 8) { st = tid*4; cnt = 4; } else { st = 32 + (tid-8)*16; cnt = 16; }
            float s = 0.f, q = 0.f;
            for (int r = st; r < st+cnt; r++) { s += rowred[2*r]; q += rowred[2*r+1]; }
            float inv = 1.f/(cnt*FSZ);
            float mean = s*inv, var = q*inv - mean*mean;
            stats[2*tid] = mean; stats[2*tid+1] = rsqrtf(var + 1e-5f);
        }
        __syncthreads();

        // normalize + store (q fp16; k fp16; v fp16)
        #pragma unroll
        for (int im = 0; im < 3; im++)
            #pragma unroll
            for (int hh = 0; hh < 2; hh++) {
                int r = wm*48 + im*16 + ly + hh*8;
                int grp = (r < 32) ? (r >> 2) : ((r >> 4) + 6);
                float mean = stats[2*grp], rstd = stats[2*grp+1];
                if (r < 32) {
                    int jrow = (r < 16) ? r : r - 16;
                    const float* gvec  = (r < 16) ? gq  : gk;
                    const float* bevec = (r < 16) ? beq : bek;
                    size_t off = (((size_t)((jrow>>2)*BSZ + b)*TSZ + t)*DQK) + (jrow&3)*FSZ;
                    __half* dst = (r < 16) ? (g_qh + off) : (g_kh + off);
                    #pragma unroll
                    for (int in = 0; in < 4; in++) {
                        int c = wn*32 + in*8 + lx*2;
                        float y0 = (acc[im][in][hh*2+0]-mean)*rstd*gvec[jrow*FSZ+c]   + bevec[jrow*FSZ+c];
                        float y1 = (acc[im][in][hh*2+1]-mean)*rstd*gvec[jrow*FSZ+c+1] + bevec[jrow*FSZ+c+1];
                        *(__half2*)(dst + c) = __floats2half2_rn(y0, y1);
                    }
                } else {
                    int jrow = r - 32;
                    __half* dst = g_vh + (((size_t)((jrow>>4)*BSZ + b)*TSZ + t)*DV) + (jrow&15)*FSZ;
                    #pragma unroll
                    for (int in = 0; in < 4; in++) {
                        int c = wn*32 + in*8 + lx*2;
                        float y0 = (acc[im][in][hh*2+0]-mean)*rstd*gv[jrow*FSZ+c]   + bev[jrow*FSZ+c];
                        float y1 = (acc[im][in][hh*2+1]-mean)*rstd*gv[jrow*FSZ+c+1] + bev[jrow*FSZ+c+1];
                        *(__half2*)(dst + c) = __floats2half2_rn(y0, y1);
                    }
                }
            }
        __syncthreads();
    }
}

// ===========================================================================
// PROJ: per block TWO t's. Y[64,128] = Wp[64,64] @ AO[64,128] per t.
//   AO is fp16 (g_aoh) -> X loaded raw via cp.async; 2-term split (W only).
// ===========================================================================
#define PJX_PITCH 272
#define PJX_T (64*PJX_PITCH)                 // 17408
#define PJ_WH 0
#define PJ_WL (64*QW_PITCH)                  // 9216
#define PJ_X  (2*64*QW_PITCH)                // 18432
#define PJ_SMEM (PJ_X + 2*PJX_T)             // 53248

__global__ void __launch_bounds__(256) proj_f16(
    const float* __restrict__ x, const float* __restrict__ Wp,
    const float* __restrict__ bp, const float* __restrict__ ap,
    const float* __restrict__ gp, const float* __restrict__ bep,
    float* __restrict__ out)
{
    extern __shared__ char sm[];
    __shared__ float red[2];
    __shared__ float statv[2];

    const int tid = threadIdx.x, lane = tid & 31, warp = tid >> 5;
    const int wm = warp >> 2, wn = warp & 3;
    const int ly = lane >> 2, lx = lane & 3;
    const int b = blockIdx.x >> 9, t0 = (blockIdx.x & 511)*2;

    const uint32_t sbase = smem_u32(sm);

    // X = AO (fp16): raw cp.async, both t's.
    #pragma unroll
    for (int j = 0; j < 8; j++) {
        int idx = tid + 256*j;
        int tt = idx >> 10, rem = idx & 1023;
        int c = rem >> 4, seg = rem & 15;
        cp16(sbase + PJ_X + tt*PJX_T + c*PJX_PITCH + seg*16,
             (const char*)(g_aoh + (((size_t)(b*CSZ + c))*TSZ + t0 + tt)*FSZ) + seg*16);
    }
    CP_COMMIT();

    // W: 64 rows x 64 floats (hi/lo)
    #pragma unroll
    for (int j = 0; j < 4; j++) {
        int idx = tid + 256*j;
        int row = idx >> 4, c4 = idx & 15;
        float4 w = *(const float4*)(Wp + row*CSZ + c4*4);
        uint2 hh, ll; split4(w, hh, ll);
        *(uint2*)(sm + PJ_WH + row*QW_PITCH + c4*8) = hh;
        *(uint2*)(sm + PJ_WL + row*QW_PITCH + c4*8) = ll;
    }
    CP_WAIT0();
    __syncthreads();

    const uint32_t awoff = sbase + PJ_WH + (wm*32 + (lane & 15))*QW_PITCH + (lane >> 4)*16;

    for (int tt = 0; tt < 2; tt++) {
        const int t = t0 + tt;
        if (tid < 2) red[tid] = 0.f;
        __syncthreads();

        const uint32_t bxoff = sbase + PJ_X + tt*PJX_T + lane*PJX_PITCH + wn*64;

        float acc[2][4][4];
        #pragma unroll
        for (int i = 0; i < 2; i++)
            #pragma unroll
            for (int j = 0; j < 4; j++)
                #pragma unroll
                for (int k = 0; k < 4; k++) acc[i][j][k] = 0.f;

        #pragma unroll
        for (int half = 0; half < 2; half++) {
            uint32_t bt[4][4];
            #pragma unroll
            for (int in = 0; in < 4; in++)
                ldsm4t(bt[in][0], bt[in][1], bt[in][2], bt[in][3],
                       bxoff + half*(32*PJX_PITCH) + in*16);
            #pragma unroll
            for (int ks = 0; ks < 2; ks++) {
                const int kstep = half*2 + ks;
                uint32_t ah[2][4], al[2][4];
                #pragma unroll
                for (int im = 0; im < 2; im++) {
                    ldsm4(ah[im][0], ah[im][1], ah[im][2], ah[im][3],
                          awoff + im*(16*QW_PITCH) + kstep*32);
                    ldsm4(al[im][0], al[im][1], al[im][2], al[im][3],
                          awoff + (PJ_WL - PJ_WH) + im*(16*QW_PITCH) + kstep*32);
                }
                #pragma unroll
                for (int im = 0; im < 2; im++)
                    #pragma unroll
                    for (int in = 0; in < 4; in++) {
                        mma16(acc[im][in], ah[im], bt[in][2*ks], bt[in][2*ks+1]);
                        mma16(acc[im][in], al[im], bt[in][2*ks], bt[in][2*ks+1]);
                    }
            }
        }

        const float alp = ap[0];
        float s1 = 0.f, s2 = 0.f;
        #pragma unroll
        for (int im = 0; im < 2; im++)
            #pragma unroll
            for (int hh = 0; hh < 2; hh++) {
                int r = wm*32 + im*16 + ly + hh*8;
                float bi = bp[r];
                #pragma unroll
                for (int in = 0; in < 4; in++)
                    #pragma unroll
                    for (int e = 0; e < 2; e++) {
                        float y = acc[im][in][hh*2+e] + bi;
                        y = y > 0.f ? y : alp*y;
                        acc[im][in][hh*2+e] = y;
                        s1 += y; s2 += y*y;
                    }
            }
        #pragma unroll
        for (int off = 16; off; off >>= 1) {
            s1 += __shfl_xor_sync(0xffffffffu, s1, off);
            s2 += __shfl_xor_sync(0xffffffffu, s2, off);
        }
        if (lane == 0) { atomicAdd(&red[0], s1); atomicAdd(&red[1], s2); }
        __syncthreads();
        if (tid == 0) {
            const float invn = 1.f/(CSZ*FSZ);
            float mean = red[0]*invn, var = red[1]*invn - mean*mean;
            statv[0] = mean; statv[1] = rsqrtf(var + 1e-5f);
        }
        __syncthreads();
        const float mean = statv[0], rstd = statv[1];

        #pragma unroll
        for (int im = 0; im < 2; im++)
            #pragma unroll
            for (int hh = 0; hh < 2; hh++) {
                int r = wm*32 + im*16 + ly + hh*8;
                size_t rowoff = (((size_t)(b*CSZ + r))*TSZ + t)*FSZ;
                #pragma unroll
                for (int in = 0; in < 4; in++) {
                    int c = wn*32 + in*8 + lx*2;
                    float2 xr = *(const float2*)(x + rowoff + c);
                    float y0 = (acc[im][in][hh*2+0]-mean)*rstd*gp[r*FSZ+c]   + bep[r*FSZ+c]   + xr.x;
                    float y1 = (acc[im][in][hh*2+1]-mean)*rstd*gp[r*FSZ+c+1] + bep[r*FSZ+c+1] + xr.y;
                    *(float2*)(out + rowoff + c) = make_float2(y0, y1);
                }
            }
        __syncthreads();
    }
}

// ===========================================================================
// Softmax: fp32 logits in, fp16 P out
// ===========================================================================
__global__ void __launch_bounds__(256) softmax_kernel()
{
    const size_t row = blockIdx.x;
    const float4* p4 = reinterpret_cast<const float4*>(g_s) + row*256;
    const int tid = threadIdx.x, lane = tid & 31, warp = tid >> 5;
    __shared__ float sred[8];

    float4 v = p4[tid];
    float m = fmaxf(fmaxf(v.x, v.y), fmaxf(v.z, v.w));
    #pragma unroll
    for (int off = 16; off; off >>= 1) m = fmaxf(m, __shfl_xor_sync(0xffffffffu, m, off));
    if (lane == 0) sred[warp] = m;
    __syncthreads();
    float mm = sred[0];
    #pragma unroll
    for (int i = 1; i < 8; i++) mm = fmaxf(mm, sred[i]);
    __syncthreads();

    v.x = __expf(v.x - mm); v.y = __expf(v.y - mm);
    v.z = __expf(v.z - mm); v.w = __expf(v.w - mm);
    float s = v.x + v.y + v.z + v.w;
    #pragma unroll
    for (int off = 16; off; off >>= 1) s += __shfl_xor_sync(0xffffffffu, s, off);
    if (lane == 0) sred[warp] = s;
    __syncthreads();
    float ss = sred[0];
    #pragma unroll
    for (int i = 1; i < 8; i++) ss += sred[i];
    float inv = 1.0f/ss;

    __half2 h0 = __floats2half2_rn(v.x*inv, v.y*inv);
    __half2 h1 = __floats2half2_rn(v.z*inv, v.w*inv);
    __half2* o2 = reinterpret_cast<__half2*>(g_sh + row*TSZ);
    o2[tid*2]   = h0;
    o2[tid*2+1] = h1;
}

// ===========================================================================
extern "C" void kernel_launch(void* const* d_in, const int* in_sizes, int n_in,
                              void* d_out, int out_size)
{
    const float* x   = (const float*)d_in[0];
    const float* Wq  = (const float*)d_in[1];
    const float* bq  = (const float*)d_in[2];
    const float* aq  = (const float*)d_in[3];
    const float* gq  = (const float*)d_in[4];
    const float* beq = (const float*)d_in[5];
    const float* Wk  = (const float*)d_in[6];
    const float* bk  = (const float*)d_in[7];
    const float* ak  = (const float*)d_in[8];
    const float* gk  = (const float*)d_in[9];
    const float* bek = (const float*)d_in[10];
    const float* Wv  = (const float*)d_in[11];
    const float* bv  = (const float*)d_in[12];
    const float* av  = (const float*)d_in[13];
    const float* gv  = (const float*)d_in[14];
    const float* bev = (const float*)d_in[15];
    const float* Wp  = (const float*)d_in[16];
    const float* bp  = (const float*)d_in[17];
    const float* ap  = (const float*)d_in[18];
    const float* gp  = (const float*)d_in[19];
    const float* bep = (const float*)d_in[20];
    float* out = (float*)d_out;

    const int SMEM_QK = 2*QK_STAGE;    // 73728
    const int SMEM_PV = 3*PV_STAGE;    // 107520
    cudaFuncSetAttribute(qkv_f16,     cudaFuncAttributeMaxDynamicSharedMemorySize, QKV_SMEM);
    cudaFuncSetAttribute(proj_f16,    cudaFuncAttributeMaxDynamicSharedMemorySize, PJ_SMEM);
    cudaFuncSetAttribute(gemm_qk_f16, cudaFuncAttributeMaxDynamicSharedMemorySize, SMEM_QK);
    cudaFuncSetAttribute(gemm_pv_f16, cudaFuncAttributeMaxDynamicSharedMemorySize, SMEM_PV);

    qkv_f16<<<BSZ*TSZ/2, 256, QKV_SMEM>>>(x, Wq, bq, aq, gq, beq,
                                          Wk, bk, ak, gk, bek,
                                          Wv, bv, av, gv, bev);
    gemm_qk_f16<<<dim3(8, 8, NB), 256, SMEM_QK>>>();
    softmax_kernel<<<NB*TSZ, 256>>>();
    gemm_pv_f16<<<dim3(16, 8, NB), 256, SMEM_PV>>>();
    proj_f16<<<BSZ*TSZ/2, 256, PJ_SMEM>>>(x, Wp, bp, ap, gp, bep, out);
}

// round 16
// speedup vs baseline: 1.2325x; 1.0018x over previous
#include <cuda_runtime.h>
#include <cuda_fp16.h>
#include <cstdint>

// Problem constants
#define BSZ 4
#define CSZ 64
#define TSZ 1024
#define FSZ 128
#define HN  4
#define HIDN 4
#define CHN 16
#define NB  (HN*BSZ)      // 16 attention batches
#define DQK (HIDN*FSZ)    // 512
#define DV  (CHN*FSZ)     // 2048

// Scratch (device globals: allocation-free rule)
__device__ __half g_qh[(size_t)NB*TSZ*DQK];          // q fp16 [n][t][d]
__device__ __half g_kh[(size_t)NB*TSZ*DQK];          // k fp16 [n][t][d]
__device__ __half g_vh[(size_t)NB*TSZ*DV];           // v fp16 [n][t][d]
__device__ float  g_s [(size_t)NB*TSZ*TSZ];          // logits fp32
__device__ __half g_sh[(size_t)NB*TSZ*TSZ];          // P fp16 [n][t][t']
__device__ __half g_aoh[(size_t)BSZ*CSZ*TSZ*FSZ];    // attention out, fp16

// ===========================================================================
// helpers
// ===========================================================================
__device__ __forceinline__ uint32_t smem_u32(const void* p) {
    uint32_t a;
    asm("{ .reg .u64 t; cvta.to.shared.u64 t, %1; cvt.u32.u64 %0, t; }" : "=r"(a) : "l"(p));
    return a;
}
__device__ __forceinline__ void ldsm4(uint32_t& r0, uint32_t& r1, uint32_t& r2, uint32_t& r3,
                                      uint32_t addr) {
    asm volatile("ldmatrix.sync.aligned.m8n8.x4.shared.b16 {%0,%1,%2,%3}, [%4];"
                 : "=r"(r0), "=r"(r1), "=r"(r2), "=r"(r3) : "r"(addr));
}
__device__ __forceinline__ void ldsm4t(uint32_t& r0, uint32_t& r1, uint32_t& r2, uint32_t& r3,
                                       uint32_t addr) {
    asm volatile("ldmatrix.sync.aligned.m8n8.x4.trans.shared.b16 {%0,%1,%2,%3}, [%4];"
                 : "=r"(r0), "=r"(r1), "=r"(r2), "=r"(r3) : "r"(addr));
}
// fp16 m16n8k16, fp32 accumulate
__device__ __forceinline__ void mma16(float* d, const uint32_t* a, uint32_t b0, uint32_t b1) {
    asm volatile("mma.sync.aligned.m16n8k16.row.col.f32.f16.f16.f32 "
                 "{%0,%1,%2,%3}, {%4,%5,%6,%7}, {%8,%9}, {%0,%1,%2,%3};"
                 : "+f"(d[0]), "+f"(d[1]), "+f"(d[2]), "+f"(d[3])
                 : "r"(a[0]), "r"(a[1]), "r"(a[2]), "r"(a[3]), "r"(b0), "r"(b1));
}
__device__ __forceinline__ void cp16(uint32_t dst, const void* src) {
    asm volatile("cp.async.cg.shared.global [%0], [%1], 16;" :: "r"(dst), "l"(src));
}
#define CP_COMMIT() asm volatile("cp.async.commit_group;" ::: "memory")
#define CP_WAIT0()  asm volatile("cp.async.wait_group 0;"  ::: "memory")
#define CP_WAIT1()  asm volatile("cp.async.wait_group 1;"  ::: "memory")

// fp16 hi/lo split of a float4 -> two packed uint2 (4 halves each)
__device__ __forceinline__ void split4(float4 v, uint2& hh, uint2& ll) {
    __half h0 = __float2half_rn(v.x), h1 = __float2half_rn(v.y);
    __half h2 = __float2half_rn(v.z), h3 = __float2half_rn(v.w);
    __half l0 = __float2half_rn(v.x - __half2float(h0));
    __half l1 = __float2half_rn(v.y - __half2float(h1));
    __half l2 = __float2half_rn(v.z - __half2float(h2));
    __half l3 = __float2half_rn(v.w - __half2float(h3));
    __half2 a = __halves2half2(h0, h1), b = __halves2half2(h2, h3);
    __half2 c = __halves2half2(l0, l1), d = __halves2half2(l2, l3);
    hh.x = *(uint32_t*)&a; hh.y = *(uint32_t*)&b;
    ll.x = *(uint32_t*)&c; ll.y = *(uint32_t*)&d;
}
// plain fp16 pack of a float4
__device__ __forceinline__ uint2 pack4(float4 v) {
    __half2 a = __floats2half2_rn(v.x, v.y);
    __half2 b = __floats2half2_rn(v.z, v.w);
    uint2 r; r.x = *(uint32_t*)&a; r.y = *(uint32_t*)&b;
    return r;
}

// ===========================================================================
// GEMM 1: S = scale * Q K^T  (single FP16, NT, 128x128, k-chunks of 64, 2-stage)
// ===========================================================================
#define QKC 64
#define QK_NCH (DQK/QKC)           // 8
#define QKP 144                    // 128B data + 16B pad
#define QK_TILE (128*QKP)          // 18432 B
#define QK_STAGE (2*QK_TILE)       // 36864 B (A, B)

__global__ void __launch_bounds__(256, 2) gemm_qk_f16()
{
    extern __shared__ char smq[];
    const int tid = threadIdx.x, lane = tid & 31, warp = tid >> 5;
    const int wm = warp >> 2, wn = warp & 3;
    const int bz = blockIdx.z, m0 = blockIdx.y*128, n0 = blockIdx.x*128;
    const __half* A = g_qh + ((size_t)bz*TSZ + m0)*DQK;
    const __half* B = g_kh + ((size_t)bz*TSZ + n0)*DQK;

    float acc[4][4][4];
    #pragma unroll
    for (int i = 0; i < 4; i++)
        #pragma unroll
        for (int j = 0; j < 4; j++)
            #pragma unroll
            for (int k = 0; k < 4; k++) acc[i][j][k] = 0.f;

    const uint32_t sbase = smem_u32(smq);
    const uint32_t aoff = (wm*64 + (lane & 15))*QKP + (lane >> 4)*16;
    const uint32_t boff = QK_TILE + (wn*32 + (lane & 7))*QKP + (lane >> 3)*16;

    auto issue = [&](int c, int s) {
        uint32_t dst = sbase + s*QK_STAGE;
        #pragma unroll
        for (int i = 0; i < 4; i++) {
            int idx = tid + 256*i;                 // 0..1023
            int row = idx >> 3, seg = idx & 7;
            uint32_t d = row*QKP + seg*16;
            size_t sa = (size_t)row*(DQK*2) + (size_t)c*(QKC*2) + seg*16;
            cp16(dst + d,           (const char*)A + sa);
            cp16(dst + QK_TILE + d, (const char*)B + sa);
        }
        CP_COMMIT();
    };

    issue(0, 0);
    for (int c = 0; c < QK_NCH; c++) {
        CP_WAIT0();
        __syncthreads();
        if (c + 1 < QK_NCH) issue(c+1, (c+1) & 1);
        const uint32_t so = sbase + (c & 1)*QK_STAGE;

        #pragma unroll
        for (int half = 0; half < 2; half++) {
            uint32_t bh[4][4];
            #pragma unroll
            for (int in = 0; in < 4; in++)
                ldsm4(bh[in][0], bh[in][1], bh[in][2], bh[in][3],
                      so + boff + half*64 + in*(8*QKP));
            #pragma unroll
            for (int ks = 0; ks < 2; ks++) {
                uint32_t a[4][4];
                #pragma unroll
                for (int im = 0; im < 4; im++)
                    ldsm4(a[im][0], a[im][1], a[im][2], a[im][3],
                          so + aoff + im*(16*QKP) + (half*2 + ks)*32);
                #pragma unroll
                for (int im = 0; im < 4; im++)
                    #pragma unroll
                    for (int in = 0; in < 4; in++)
                        mma16(acc[im][in], a[im], bh[in][2*ks], bh[in][2*ks+1]);
            }
        }
    }

    const float scale = 0.0441941738241592f;   // 1/sqrt(512)
    float* Cb = g_s + (size_t)bz*TSZ*TSZ;
    const int mbase = m0 + wm*64, nbase = n0 + wn*32;
    #pragma unroll
    for (int im = 0; im < 4; im++)
        #pragma unroll
        for (int in = 0; in < 4; in++) {
            int rr = mbase + im*16 + (lane >> 2);
            int cc = nbase + in*8 + (lane & 3)*2;
            float2 o0 = make_float2(acc[im][in][0]*scale, acc[im][in][1]*scale);
            float2 o1 = make_float2(acc[im][in][2]*scale, acc[im][in][3]*scale);
            *(float2*)(Cb + (size_t)rr*TSZ + cc)     = o0;
            *(float2*)(Cb + (size_t)(rr+8)*TSZ + cc) = o1;
        }
}

// ===========================================================================
// GEMM 2: O = P V  (single FP16; V via ldmatrix.trans; K-chunk 64; 3-stage)
//   Epilogue writes fp16 AO directly (g_aoh).
// ===========================================================================
#define PVC 64
#define PV_NCH (TSZ/PVC)           // 16
#define PVA_PITCH 144
#define PVB_PITCH 272
#define PVA_TILE (128*PVA_PITCH)   // 18432
#define PVB_TILE (64*PVB_PITCH)    // 17408
#define PV_STAGE (PVA_TILE + PVB_TILE)  // 35840

__global__ void __launch_bounds__(256, 2) gemm_pv_f16()
{
    extern __shared__ char smp[];
    const int tid = threadIdx.x, lane = tid & 31, warp = tid >> 5;
    const int wm = warp >> 2, wn = warp & 3;
    const int bz = blockIdx.z, m0 = blockIdx.y*128, n0 = blockIdx.x*128;
    const __half* A = g_sh + (size_t)bz*TSZ*TSZ + (size_t)m0*TSZ;
    const __half* B = g_vh + (size_t)bz*TSZ*DV;

    float acc[4][4][4];
    #pragma unroll
    for (int i = 0; i < 4; i++)
        #pragma unroll
        for (int j = 0; j < 4; j++)
            #pragma unroll
            for (int k = 0; k < 4; k++) acc[i][j][k] = 0.f;

    const uint32_t sbase = smem_u32(smp);
    const uint32_t aoff = (wm*64 + (lane & 15))*PVA_PITCH + (lane >> 4)*16;
    const uint32_t btoff = PVA_TILE + lane*PVB_PITCH + wn*64;

    auto issue = [&](int c, int s) {
        uint32_t dst = sbase + s*PV_STAGE;
        #pragma unroll
        for (int i = 0; i < 4; i++) {
            int idx = tid + 256*i;
            int ar = idx >> 3, as = idx & 7;
            cp16(dst + ar*PVA_PITCH + as*16,
                 (const char*)A + (size_t)ar*(TSZ*2) + (size_t)c*(PVC*2) + as*16);
            int br = idx >> 4, bs = idx & 15;
            cp16(dst + PVA_TILE + br*PVB_PITCH + bs*16,
                 (const char*)B + ((size_t)(c*PVC + br))*(DV*2) + (size_t)n0*2 + bs*16);
        }
        CP_COMMIT();
    };

    issue(0, 0);
    issue(1, 1);
    for (int c = 0; c < PV_NCH; c++) {
        if (c + 1 < PV_NCH) CP_WAIT1();
        else                CP_WAIT0();
        __syncthreads();
        if (c + 2 < PV_NCH) issue(c+2, (c+2) % 3);
        const uint32_t so = sbase + (c % 3)*PV_STAGE;

        #pragma unroll
        for (int half = 0; half < 2; half++) {
            uint32_t bt[4][4];
            #pragma unroll
            for (int in = 0; in < 4; in++)
                ldsm4t(bt[in][0], bt[in][1], bt[in][2], bt[in][3],
                       so + btoff + half*(32*PVB_PITCH) + in*16);
            #pragma unroll
            for (int ks = 0; ks < 2; ks++) {
                uint32_t a[4][4];
                #pragma unroll
                for (int im = 0; im < 4; im++)
                    ldsm4(a[im][0], a[im][1], a[im][2], a[im][3],
                          so + aoff + im*(16*PVA_PITCH) + (half*2 + ks)*32);
                #pragma unroll
                for (int im = 0; im < 4; im++)
                    #pragma unroll
                    for (int in = 0; in < 4; in++)
                        mma16(acc[im][in], a[im], bt[in][2*ks], bt[in][2*ks+1]);
            }
        }
    }

    const int h = bz >> 2, bb = bz & 3;
    const int cc_ch = h*CHN + blockIdx.x;
    const int mbase = m0 + wm*64, nbase = wn*32;
    __half* Ob = g_aoh + ((size_t)(bb*CSZ + cc_ch)*TSZ)*FSZ;
    #pragma unroll
    for (int im = 0; im < 4; im++)
        #pragma unroll
        for (int in = 0; in < 4; in++) {
            int rr = mbase + im*16 + (lane >> 2);
            int ff = nbase + in*8 + (lane & 3)*2;
            *(__half2*)(Ob + (size_t)rr*FSZ + ff) =
                __floats2half2_rn(acc[im][in][0], acc[im][in][1]);
            *(__half2*)(Ob + (size_t)(rr+8)*FSZ + ff) =
                __floats2half2_rn(acc[im][in][2], acc[im][in][3]);
        }
}

// ===========================================================================
// QKV: per block handles TWO t's. Y[96,128] = Wall[96,64] @ X[64,128] per t.
//   2-term fp16: (Wh+Wl)·x with x fp16-rounded. W converted once.
// ===========================================================================
#define QW_PITCH 144               // 128B (64 halves) + 16 pad
#define QX_PITCH 272               // 256B (128 halves) + 16 pad
#define QX_T (64*QX_PITCH)         // one t's X tile: 17408
#define QKV_WH 0
#define QKV_WL (96*QW_PITCH)                 // 13824
#define QKV_X  (2*96*QW_PITCH)               // 27648
#define QKV_SMEM (QKV_X + 2*QX_T)            // 62464

__global__ void __launch_bounds__(256) qkv_f16(
    const float* __restrict__ x,
    const float* __restrict__ Wq, const float* __restrict__ bq,
    const float* __restrict__ aq, const float* __restrict__ gq, const float* __restrict__ beq,
    const float* __restrict__ Wk, const float* __restrict__ bk,
    const float* __restrict__ ak, const float* __restrict__ gk, const float* __restrict__ bek,
    const float* __restrict__ Wv, const float* __restrict__ bv,
    const float* __restrict__ av, const float* __restrict__ gv, const float* __restrict__ bev)
{
    extern __shared__ char sm[];
    __shared__ float rowred[96*2];
    __shared__ float stats[12*2];
    __shared__ float biasS[96], alphS[96];

    const int tid = threadIdx.x, lane = tid & 31, warp = tid >> 5;
    const int wm = warp >> 2, wn = warp & 3;
    const int ly = lane >> 2, lx = lane & 3;
    const int b = blockIdx.x >> 9, t0 = (blockIdx.x & 511)*2;

    if (tid < 96) {
        if (tid < 16)      { biasS[tid] = bq[tid];    alphS[tid] = aq[tid>>2]; }
        else if (tid < 32) { biasS[tid] = bk[tid-16]; alphS[tid] = ak[(tid-16)>>2]; }
        else               { biasS[tid] = bv[tid-32]; alphS[tid] = av[(tid-32)>>4]; }
    }

    // W: 96 rows x 64 floats -> fp16 hi/lo (converted ONCE for both t's)
    #pragma unroll
    for (int j = 0; j < 6; j++) {
        int idx = tid + 256*j;
        int row = idx >> 4, c4 = idx & 15;
        const float* src;
        if (row < 16)      src = Wq + row*CSZ;
        else if (row < 32) src = Wk + (row-16)*CSZ;
        else               src = Wv + (row-32)*CSZ;
        float4 w = *(const float4*)(src + c4*4);
        uint2 hh, ll; split4(w, hh, ll);
        *(uint2*)(sm + QKV_WH + row*QW_PITCH + c4*8) = hh;
        *(uint2*)(sm + QKV_WL + row*QW_PITCH + c4*8) = ll;
    }
    // X: both t's, single fp16: 2 x 64 c-rows x 128 f (4096 float4, 16/thread)
    #pragma unroll
    for (int j = 0; j < 16; j++) {
        int idx = tid + 256*j;
        int tt = idx >> 11, rem = idx & 2047;
        int c = rem >> 5, f4 = rem & 31;
        float4 v = *(const float4*)(x + (((size_t)(b*CSZ + c))*TSZ + t0 + tt)*FSZ + f4*4);
        *(uint2*)(sm + QKV_X + tt*QX_T + c*QX_PITCH + f4*8) = pack4(v);
    }
    __syncthreads();

    const uint32_t sbase = smem_u32(sm);
    const uint32_t awoff = sbase + QKV_WH + (wm*48 + (lane & 15))*QW_PITCH + (lane >> 4)*16;

    for (int tt = 0; tt < 2; tt++) {
        const int t = t0 + tt;
        if (tid < 192) rowred[tid] = 0.f;
        __syncthreads();

        const uint32_t bxoff = sbase + QKV_X + tt*QX_T + lane*QX_PITCH + wn*64;

        float acc[3][4][4];
        #pragma unroll
        for (int i = 0; i < 3; i++)
            #pragma unroll
            for (int j = 0; j < 4; j++)
                #pragma unroll
                for (int k = 0; k < 4; k++) acc[i][j][k] = 0.f;

        #pragma unroll
        for (int half = 0; half < 2; half++) {
            uint32_t bt[4][4];
            #pragma unroll
            for (int in = 0; in < 4; in++)
                ldsm4t(bt[in][0], bt[in][1], bt[in][2], bt[in][3],
                       bxoff + half*(32*QX_PITCH) + in*16);
            #pragma unroll
            for (int ks = 0; ks < 2; ks++) {
                const int kstep = half*2 + ks;
                uint32_t ah[3][4], al[3][4];
                #pragma unroll
                for (int im = 0; im < 3; im++) {
                    ldsm4(ah[im][0], ah[im][1], ah[im][2], ah[im][3],
                          awoff + im*(16*QW_PITCH) + kstep*32);
                    ldsm4(al[im][0], al[im][1], al[im][2], al[im][3],
                          awoff + (QKV_WL - QKV_WH) + im*(16*QW_PITCH) + kstep*32);
                }
                #pragma unroll
                for (int im = 0; im < 3; im++)
                    #pragma unroll
                    for (int in = 0; in < 4; in++) {
                        mma16(acc[im][in], ah[im], bt[in][2*ks], bt[in][2*ks+1]);
                        mma16(acc[im][in], al[im], bt[in][2*ks], bt[in][2*ks+1]);
                    }
            }
        }

        // bias + PReLU + per-row partial sums
        float rs[3][2], rq[3][2];
        #pragma unroll
        for (int im = 0; im < 3; im++) { rs[im][0]=rs[im][1]=0.f; rq[im][0]=rq[im][1]=0.f; }
        #pragma unroll
        for (int im = 0; im < 3; im++)
            #pragma unroll
            for (int hh = 0; hh < 2; hh++) {
                int r = wm*48 + im*16 + ly + hh*8;
                float bi = biasS[r], alp = alphS[r];
                #pragma unroll
                for (int in = 0; in < 4; in++)
                    #pragma unroll
                    for (int e = 0; e < 2; e++) {
                        float y = acc[im][in][hh*2+e] + bi;
                        y = y > 0.f ? y : alp*y;
                        acc[im][in][hh*2+e] = y;
                        rs[im][hh] += y; rq[im][hh] += y*y;
                    }
            }
        #pragma unroll
        for (int im = 0; im < 3; im++)
            #pragma unroll
            for (int hh = 0; hh < 2; hh++) {
                float s = rs[im][hh], q = rq[im][hh];
                s += __shfl_xor_sync(0xffffffffu, s, 1); q += __shfl_xor_sync(0xffffffffu, q, 1);
                s += __shfl_xor_sync(0xffffffffu, s, 2); q += __shfl_xor_sync(0xffffffffu, q, 2);
                if (lx == 0) {
                    int r = wm*48 + im*16 + ly + hh*8;
                    atomicAdd(&rowred[2*r], s); atomicAdd(&rowred[2*r+1], q);
                }
            }
        __syncthreads();
        if (tid < 12) {
            int st, cnt;
            if (tid < 8) { st = tid*4; cnt = 4; } else { st = 32 + (tid-8)*16; cnt = 16; }
            float s = 0.f, q = 0.f;
            for (int r = st; r < st+cnt; r++) { s += rowred[2*r]; q += rowred[2*r+1]; }
            float inv = 1.f/(cnt*FSZ);
            float mean = s*inv, var = q*inv - mean*mean;
            stats[2*tid] = mean; stats[2*tid+1] = rsqrtf(var + 1e-5f);
        }
        __syncthreads();

        // normalize + store (q fp16; k fp16; v fp16)
        #pragma unroll
        for (int im = 0; im < 3; im++)
            #pragma unroll
            for (int hh = 0; hh < 2; hh++) {
                int r = wm*48 + im*16 + ly + hh*8;
                int grp = (r < 32) ? (r >> 2) : ((r >> 4) + 6);
                float mean = stats[2*grp], rstd = stats[2*grp+1];
                if (r < 32) {
                    int jrow = (r < 16) ? r : r - 16;
                    const float* gvec  = (r < 16) ? gq  : gk;
                    const float* bevec = (r < 16) ? beq : bek;
                    size_t off = (((size_t)((jrow>>2)*BSZ + b)*TSZ + t)*DQK) + (jrow&3)*FSZ;
                    __half* dst = (r < 16) ? (g_qh + off) : (g_kh + off);
                    #pragma unroll
                    for (int in = 0; in < 4; in++) {
                        int c = wn*32 + in*8 + lx*2;
                        float y0 = (acc[im][in][hh*2+0]-mean)*rstd*gvec[jrow*FSZ+c]   + bevec[jrow*FSZ+c];
                        float y1 = (acc[im][in][hh*2+1]-mean)*rstd*gvec[jrow*FSZ+c+1] + bevec[jrow*FSZ+c+1];
                        *(__half2*)(dst + c) = __floats2half2_rn(y0, y1);
                    }
                } else {
                    int jrow = r - 32;
                    __half* dst = g_vh + (((size_t)((jrow>>4)*BSZ + b)*TSZ + t)*DV) + (jrow&15)*FSZ;
                    #pragma unroll
                    for (int in = 0; in < 4; in++) {
                        int c = wn*32 + in*8 + lx*2;
                        float y0 = (acc[im][in][hh*2+0]-mean)*rstd*gv[jrow*FSZ+c]   + bev[jrow*FSZ+c];
                        float y1 = (acc[im][in][hh*2+1]-mean)*rstd*gv[jrow*FSZ+c+1] + bev[jrow*FSZ+c+1];
                        *(__half2*)(dst + c) = __floats2half2_rn(y0, y1);
                    }
                }
            }
        __syncthreads();
    }
}

// ===========================================================================
// PROJ: per block TWO t's. Y[64,128] = Wp[64,64] @ AO[64,128] per t.
//   Single fp16 GEMM (W fp16-rounded, AO fp16 raw via cp.async).
// ===========================================================================
#define PJX_PITCH 272
#define PJX_T (64*PJX_PITCH)                 // 17408
#define PJ_W  0
#define PJ_X  (64*QW_PITCH)                  // 9216
#define PJ_SMEM (PJ_X + 2*PJX_T)             // 44032

__global__ void __launch_bounds__(256) proj_f16(
    const float* __restrict__ x, const float* __restrict__ Wp,
    const float* __restrict__ bp, const float* __restrict__ ap,
    const float* __restrict__ gp, const float* __restrict__ bep,
    float* __restrict__ out)
{
    extern __shared__ char sm[];
    __shared__ float red[2];
    __shared__ float statv[2];

    const int tid = threadIdx.x, lane = tid & 31, warp = tid >> 5;
    const int wm = warp >> 2, wn = warp & 3;
    const int ly = lane >> 2, lx = lane & 3;
    const int b = blockIdx.x >> 9, t0 = (blockIdx.x & 511)*2;

    const uint32_t sbase = smem_u32(sm);

    // X = AO (fp16): raw cp.async, both t's.
    #pragma unroll
    for (int j = 0; j < 8; j++) {
        int idx = tid + 256*j;
        int tt = idx >> 10, rem = idx & 1023;
        int c = rem >> 4, seg = rem & 15;
        cp16(sbase + PJ_X + tt*PJX_T + c*PJX_PITCH + seg*16,
             (const char*)(g_aoh + (((size_t)(b*CSZ + c))*TSZ + t0 + tt)*FSZ) + seg*16);
    }
    CP_COMMIT();

    // W: 64 rows x 64 floats -> single fp16
    #pragma unroll
    for (int j = 0; j < 4; j++) {
        int idx = tid + 256*j;
        int row = idx >> 4, c4 = idx & 15;
        float4 w = *(const float4*)(Wp + row*CSZ + c4*4);
        *(uint2*)(sm + PJ_W + row*QW_PITCH + c4*8) = pack4(w);
    }
    CP_WAIT0();
    __syncthreads();

    const uint32_t awoff = sbase + PJ_W + (wm*32 + (lane & 15))*QW_PITCH + (lane >> 4)*16;

    for (int tt = 0; tt < 2; tt++) {
        const int t = t0 + tt;
        if (tid < 2) red[tid] = 0.f;
        __syncthreads();

        const uint32_t bxoff = sbase + PJ_X + tt*PJX_T + lane*PJX_PITCH + wn*64;

        float acc[2][4][4];
        #pragma unroll
        for (int i = 0; i < 2; i++)
            #pragma unroll
            for (int j = 0; j < 4; j++)
                #pragma unroll
                for (int k = 0; k < 4; k++) acc[i][j][k] = 0.f;

        #pragma unroll
        for (int half = 0; half < 2; half++) {
            uint32_t bt[4][4];
            #pragma unroll
            for (int in = 0; in < 4; in++)
                ldsm4t(bt[in][0], bt[in][1], bt[in][2], bt[in][3],
                       bxoff + half*(32*PJX_PITCH) + in*16);
            #pragma unroll
            for (int ks = 0; ks < 2; ks++) {
                const int kstep = half*2 + ks;
                uint32_t a[2][4];
                #pragma unroll
                for (int im = 0; im < 2; im++)
                    ldsm4(a[im][0], a[im][1], a[im][2], a[im][3],
                          awoff + im*(16*QW_PITCH) + kstep*32);
                #pragma unroll
                for (int im = 0; im < 2; im++)
                    #pragma unroll
                    for (int in = 0; in < 4; in++)
                        mma16(acc[im][in], a[im], bt[in][2*ks], bt[in][2*ks+1]);
            }
        }

        const float alp = ap[0];
        float s1 = 0.f, s2 = 0.f;
        #pragma unroll
        for (int im = 0; im < 2; im++)
            #pragma unroll
            for (int hh = 0; hh < 2; hh++) {
                int r = wm*32 + im*16 + ly + hh*8;
                float bi = bp[r];
                #pragma unroll
                for (int in = 0; in < 4; in++)
                    #pragma unroll
                    for (int e = 0; e < 2; e++) {
                        float y = acc[im][in][hh*2+e] + bi;
                        y = y > 0.f ? y : alp*y;
                        acc[im][in][hh*2+e] = y;
                        s1 += y; s2 += y*y;
                    }
            }
        #pragma unroll
        for (int off = 16; off; off >>= 1) {
            s1 += __shfl_xor_sync(0xffffffffu, s1, off);
            s2 += __shfl_xor_sync(0xffffffffu, s2, off);
        }
        if (lane == 0) { atomicAdd(&red[0], s1); atomicAdd(&red[1], s2); }
        __syncthreads();
        if (tid == 0) {
            const float invn = 1.f/(CSZ*FSZ);
            float mean = red[0]*invn, var = red[1]*invn - mean*mean;
            statv[0] = mean; statv[1] = rsqrtf(var + 1e-5f);
        }
        __syncthreads();
        const float mean = statv[0], rstd = statv[1];

        #pragma unroll
        for (int im = 0; im < 2; im++)
            #pragma unroll
            for (int hh = 0; hh < 2; hh++) {
                int r = wm*32 + im*16 + ly + hh*8;
                size_t rowoff = (((size_t)(b*CSZ + r))*TSZ + t)*FSZ;
                #pragma unroll
                for (int in = 0; in < 4; in++) {
                    int c = wn*32 + in*8 + lx*2;
                    float2 xr = *(const float2*)(x + rowoff + c);
                    float y0 = (acc[im][in][hh*2+0]-mean)*rstd*gp[r*FSZ+c]   + bep[r*FSZ+c]   + xr.x;
                    float y1 = (acc[im][in][hh*2+1]-mean)*rstd*gp[r*FSZ+c+1] + bep[r*FSZ+c+1] + xr.y;
                    *(float2*)(out + rowoff + c) = make_float2(y0, y1);
                }
            }
        __syncthreads();
    }
}

// ===========================================================================
// Softmax: fp32 logits in, fp16 P out
// ===========================================================================
__global__ void __launch_bounds__(256) softmax_kernel()
{
    const size_t row = blockIdx.x;
    const float4* p4 = reinterpret_cast<const float4*>(g_s) + row*256;
    const int tid = threadIdx.x, lane = tid & 31, warp = tid >> 5;
    __shared__ float sred[8];

    float4 v = p4[tid];
    float m = fmaxf(fmaxf(v.x, v.y), fmaxf(v.z, v.w));
    #pragma unroll
    for (int off = 16; off; off >>= 1) m = fmaxf(m, __shfl_xor_sync(0xffffffffu, m, off));
    if (lane == 0) sred[warp] = m;
    __syncthreads();
    float mm = sred[0];
    #pragma unroll
    for (int i = 1; i < 8; i++) mm = fmaxf(mm, sred[i]);
    __syncthreads();

    v.x = __expf(v.x - mm); v.y = __expf(v.y - mm);
    v.z = __expf(v.z - mm); v.w = __expf(v.w - mm);
    float s = v.x + v.y + v.z + v.w;
    #pragma unroll
    for (int off = 16; off; off >>= 1) s += __shfl_xor_sync(0xffffffffu, s, off);
    if (lane == 0) sred[warp] = s;
    __syncthreads();
    float ss = sred[0];
    #pragma unroll
    for (int i = 1; i < 8; i++) ss += sred[i];
    float inv = 1.0f/ss;

    __half2 h0 = __floats2half2_rn(v.x*inv, v.y*inv);
    __half2 h1 = __floats2half2_rn(v.z*inv, v.w*inv);
    __half2* o2 = reinterpret_cast<__half2*>(g_sh + row*TSZ);
    o2[tid*2]   = h0;
    o2[tid*2+1] = h1;
}

// ===========================================================================
extern "C" void kernel_launch(void* const* d_in, const int* in_sizes, int n_in,
                              void* d_out, int out_size)
{
    const float* x   = (const float*)d_in[0];
    const float* Wq  = (const float*)d_in[1];
    const float* bq  = (const float*)d_in[2];
    const float* aq  = (const float*)d_in[3];
    const float* gq  = (const float*)d_in[4];
    const float* beq = (const float*)d_in[5];
    const float* Wk  = (const float*)d_in[6];
    const float* bk  = (const float*)d_in[7];
    const float* ak  = (const float*)d_in[8];
    const float* gk  = (const float*)d_in[9];
    const float* bek = (const float*)d_in[10];
    const float* Wv  = (const float*)d_in[11];
    const float* bv  = (const float*)d_in[12];
    const float* av  = (const float*)d_in[13];
    const float* gv  = (const float*)d_in[14];
    const float* bev = (const float*)d_in[15];
    const float* Wp  = (const float*)d_in[16];
    const float* bp  = (const float*)d_in[17];
    const float* ap  = (const float*)d_in[18];
    const float* gp  = (const float*)d_in[19];
    const float* bep = (const float*)d_in[20];
    float* out = (float*)d_out;

    const int SMEM_QK = 2*QK_STAGE;    // 73728
    const int SMEM_PV = 3*PV_STAGE;    // 107520
    cudaFuncSetAttribute(qkv_f16,     cudaFuncAttributeMaxDynamicSharedMemorySize, QKV_SMEM);
    cudaFuncSetAttribute(proj_f16,    cudaFuncAttributeMaxDynamicSharedMemorySize, PJ_SMEM);
    cudaFuncSetAttribute(gemm_qk_f16, cudaFuncAttributeMaxDynamicSharedMemorySize, SMEM_QK);
    cudaFuncSetAttribute(gemm_pv_f16, cudaFuncAttributeMaxDynamicSharedMemorySize, SMEM_PV);

    qkv_f16<<<BSZ*TSZ/2, 256, QKV_SMEM>>>(x, Wq, bq, aq, gq, beq,
                                          Wk, bk, ak, gk, bek,
                                          Wv, bv, av, gv, bev);
    gemm_qk_f16<<<dim3(8, 8, NB), 256, SMEM_QK>>>();
    softmax_kernel<<<NB*TSZ, 256>>>();
    gemm_pv_f16<<<dim3(16, 8, NB), 256, SMEM_PV>>>();
    proj_f16<<<BSZ*TSZ/2, 256, PJ_SMEM>>>(x, Wp, bp, ap, gp, bep, out);
}